// round 9
// baseline (speedup 1.0000x reference)
#include <cuda_runtime.h>
#include <math.h>
#include <stdint.h>

// Problem constants (fixed shapes)
#define BQ 4
#define LQ 4096
#define DQ 512
#define NQ 64
#define MQ (BQ * LQ)        // 16384 rows
#define NBLK 256            // (b,chunk) blocks, chunk=64

typedef unsigned long long ull;

// -------- scratch (device globals; no allocation allowed) --------
__device__ float g_xp[(size_t)MQ * 1024];        // xproj out: x_bar [0,512), z [512,1024)
__device__ float g_xt[(size_t)MQ * 512];         // tf32-rounded x
__device__ float g_xbt[(size_t)MQ * 512];        // tf32-rounded x_bar
__device__ float g_Bm[(size_t)MQ * 64];          // B proj (rmsnormed)
__device__ float g_Cm[(size_t)MQ * 64];          // C proj (rmsnormed)
__device__ float g_ax[(size_t)MQ * 512];         // a=exp(la); overwritten w/ cumulative decay
__device__ float g_Yb[(size_t)MQ * 512];         // y buffer (h stored tf32-rounded)
__device__ float g_cs[(size_t)NBLK * 64 * 512];  // chunk states -> prev states
__device__ float g_dtot[(size_t)NBLK * 512];     // per-chunk total decay
__device__ float g_Ac[512];                      // A coefficient
// transposed tf32 weights: Wt[n][k], k contiguous (512)
__device__ float g_Wt_xp[1024 * 512];
__device__ float g_Wt_dt[512 * 512];
__device__ float g_Wt_out[512 * 512];
__device__ float g_Wt_bc[128 * 512];             // rows 0..63 = W_B^T, 64..127 = W_C^T

// ============================ helpers ============================
__device__ __forceinline__ uint32_t f2tf32(float x) {
    uint32_t u;
    asm("cvt.rna.tf32.f32 %0, %1;" : "=r"(u) : "f"(x));
    return u;
}
__device__ __forceinline__ void mma_tf32(float* d, const uint32_t* a, const uint32_t* b) {
    asm volatile(
        "mma.sync.aligned.m16n8k8.row.col.f32.tf32.tf32.f32 "
        "{%0,%1,%2,%3}, {%4,%5,%6,%7}, {%8,%9}, {%0,%1,%2,%3};"
        : "+f"(d[0]), "+f"(d[1]), "+f"(d[2]), "+f"(d[3])
        : "r"(a[0]), "r"(a[1]), "r"(a[2]), "r"(a[3]), "r"(b[0]), "r"(b[1]));
}
__device__ __forceinline__ float dt_transform(float v, float Acoef) {
    float sp  = (v > 20.0f) ? v : log1pf(expf(v));
    float dtv = fminf(fmaxf(sp, 1e-4f), 5.0f);
    float la  = fminf(fmaxf(dtv * Acoef, -18.4206807f), 0.0f);
    return expf(la);
}
__device__ __forceinline__ void cpasync16(uint32_t saddr, const void* g) {
    asm volatile("cp.async.cg.shared.global [%0], [%1], 16;" :: "r"(saddr), "l"(g));
}
#define CP_COMMIT() asm volatile("cp.async.commit_group;" ::: "memory")
#define CP_WAIT1()  asm volatile("cp.async.wait_group 1;" ::: "memory")
#define CP_WAIT0()  asm volatile("cp.async.wait_group 0;" ::: "memory")

__device__ __forceinline__ ull pack2(float lo, float hi) {
    ull r; asm("mov.b64 %0, {%1, %2};" : "=l"(r) : "f"(lo), "f"(hi)); return r;
}
__device__ __forceinline__ void unpack2(ull v, float& lo, float& hi) {
    asm("mov.b64 {%0, %1}, %2;" : "=f"(lo), "=f"(hi) : "l"(v));
}
#define FMA2_ACC(d, a, b) \
    asm("fma.rn.f32x2 %0, %1, %2, %0;" : "+l"(d) : "l"(a), "l"(b))
#define MUL2(d, a, b) \
    asm("mul.rn.f32x2 %0, %1, %2;" : "=l"(d) : "l"(a), "l"(b))

// ============================ GEMM mainloop (3-stage, 1 barrier/chunk) ============
// D[128,128] tile = A[row0..+128, 0..512)(lda) * Bt[col0..+128, 0..512)^T.
// 8 warps (2 M x 4 N), warp tile 64x32, m16n8k8, scalar 32-bit LDS fragments.
// 3 SMEM stages; issue for chunk c+2 targets stage (c-1)%3 whose readers all
// passed this iteration's barrier -> single __syncthreads per chunk.
#define STG_F (128 * 36)
#define NSTG 3

__device__ __forceinline__ void gemm_mainloop(
    const float* __restrict__ A, int lda, const float* __restrict__ Bt,
    int row0, int col0, float* sm, float acc[4][4][4],
    int tid, int warp_m, int warp_n, int g, int tig)
{
    float* Asm = sm;                 // NSTG stages x 128x36
    float* Bsm = sm + NSTG * STG_F;
    const uint32_t asm_u = (uint32_t)__cvta_generic_to_shared(Asm);
    const uint32_t bsm_u = (uint32_t)__cvta_generic_to_shared(Bsm);
    const int ldm = tid >> 3;
    const int ldk4 = tid & 7;

    auto issue = [&](int s, int k0) {
        #pragma unroll
        for (int j = 0; j < 4; j++) {
            const int m = ldm + 32 * j;
            const uint32_t off = (uint32_t)((s * STG_F + m * 36 + ldk4 * 4) * 4);
            cpasync16(asm_u + off, &A[(size_t)(row0 + m) * lda + k0 + ldk4 * 4]);
            cpasync16(bsm_u + off, &Bt[(size_t)(col0 + m) * 512 + k0 + ldk4 * 4]);
        }
        CP_COMMIT();
    };
    issue(0, 0);
    issue(1, 32);

    #pragma unroll 1
    for (int c = 0; c < 16; c++) {
        const int s = c % NSTG;
        if (c < 15) { CP_WAIT1(); } else { CP_WAIT0(); }
        __syncthreads();
        if (c + 2 < 16) issue((c + 2) % NSTG, (c + 2) * 32);
        const uint32_t* AsU = (const uint32_t*)(Asm + s * STG_F);
        const uint32_t* BsU = (const uint32_t*)(Bsm + s * STG_F);
        #pragma unroll
        for (int kk = 0; kk < 4; kk++) {
            const int k = kk * 8;
            uint32_t af[4][4];
            #pragma unroll
            for (int mi = 0; mi < 4; mi++) {
                const int mr = warp_m * 64 + mi * 16 + g;
                af[mi][0] = AsU[mr * 36 + k + tig];
                af[mi][1] = AsU[(mr + 8) * 36 + k + tig];
                af[mi][2] = AsU[mr * 36 + k + tig + 4];
                af[mi][3] = AsU[(mr + 8) * 36 + k + tig + 4];
            }
            #pragma unroll
            for (int ni = 0; ni < 4; ni++) {
                uint32_t bf[2];
                const int nr = warp_n * 32 + ni * 8 + g;
                bf[0] = BsU[nr * 36 + k + tig];
                bf[1] = BsU[nr * 36 + k + tig + 4];
                #pragma unroll
                for (int mi = 0; mi < 4; mi++)
                    mma_tf32(acc[mi][ni], af[mi], bf);
            }
        }
    }
    __syncthreads();
}

// ---- EPI 0: +bias -> out0.  EPI 3: xproj (+bias -> out0 ld 1024; cols<512 also
//      tf32-rounded -> out1 ld 512)
template <int EPI>
__global__ void __launch_bounds__(256, 2)
mma_gemm_k(const float* __restrict__ A, int lda,
           const float* __restrict__ Bt,
           const float* __restrict__ bias,
           float* __restrict__ out0, float* __restrict__ out1, int ldc)
{
    extern __shared__ float sm[];
    const int tid = threadIdx.x;
    const int wid = tid >> 5;
    const int lane = tid & 31;
    const int g = lane >> 2;
    const int tig = lane & 3;
    const int warp_m = wid >> 2;
    const int warp_n = wid & 3;
    const int row0 = blockIdx.y * 128;
    const int col0 = blockIdx.x * 128;

    float acc[4][4][4] = {};
    gemm_mainloop(A, lda, Bt, row0, col0, sm, acc, tid, warp_m, warp_n, g, tig);

    #pragma unroll
    for (int mi = 0; mi < 4; mi++) {
        const int m = row0 + warp_m * 64 + mi * 16 + g;
        #pragma unroll
        for (int ni = 0; ni < 4; ni++) {
            const int n = col0 + warp_n * 32 + ni * 8 + 2 * tig;
            float d0 = acc[mi][ni][0], d1 = acc[mi][ni][1];
            float d2 = acc[mi][ni][2], d3 = acc[mi][ni][3];
            const float b0 = bias[n], b1 = bias[n + 1];
            d0 += b0; d1 += b1; d2 += b0; d3 += b1;
            *(float2*)&out0[(size_t)m * ldc + n] = make_float2(d0, d1);
            *(float2*)&out0[(size_t)(m + 8) * ldc + n] = make_float2(d2, d3);
            if (EPI == 3 && n < 512) {
                *(float2*)&out1[(size_t)m * 512 + n] = make_float2(
                    __uint_as_float(f2tf32(d0)), __uint_as_float(f2tf32(d1)));
                *(float2*)&out1[(size_t)(m + 8) * 512 + n] = make_float2(
                    __uint_as_float(f2tf32(d2)), __uint_as_float(f2tf32(d3)));
            }
        }
    }
}

// ---- merged dt (blockIdx.x<4) + fused B|C rmsnorm (blockIdx.x==4) ----
__global__ void __launch_bounds__(256, 2)
dtbc_gemm_k(const float* __restrict__ xbt,
            const float* __restrict__ Wdt, const float* __restrict__ Wbc,
            const float* __restrict__ dt_bias, const float* __restrict__ Ac,
            float* __restrict__ ax,
            float* __restrict__ Bm, float* __restrict__ Cm,
            const float* __restrict__ gBn, const float* __restrict__ gCn)
{
    extern __shared__ float sm[];
    __shared__ float ssred[256];
    const int tid = threadIdx.x;
    const int wid = tid >> 5;
    const int lane = tid & 31;
    const int g = lane >> 2;
    const int tig = lane & 3;
    const int warp_m = wid >> 2;
    const int warp_n = wid & 3;
    const int row0 = blockIdx.y * 128;
    const bool is_dt = blockIdx.x < 4;
    const int col0 = is_dt ? blockIdx.x * 128 : 0;
    const float* Bt = is_dt ? Wdt : Wbc;

    if (!is_dt) ssred[tid] = 0.0f;

    float acc[4][4][4] = {};
    gemm_mainloop(xbt, 512, Bt, row0, col0, sm, acc, tid, warp_m, warp_n, g, tig);

    if (is_dt) {
        #pragma unroll
        for (int mi = 0; mi < 4; mi++) {
            const int m = row0 + warp_m * 64 + mi * 16 + g;
            #pragma unroll
            for (int ni = 0; ni < 4; ni++) {
                const int n = col0 + warp_n * 32 + ni * 8 + 2 * tig;
                const float b0 = dt_bias[n], b1 = dt_bias[n + 1];
                const float a0 = Ac[n], a1 = Ac[n + 1];
                *(float2*)&ax[(size_t)m * 512 + n] = make_float2(
                    dt_transform(acc[mi][ni][0] + b0, a0),
                    dt_transform(acc[mi][ni][1] + b1, a1));
                *(float2*)&ax[(size_t)(m + 8) * 512 + n] = make_float2(
                    dt_transform(acc[mi][ni][2] + b0, a0),
                    dt_transform(acc[mi][ni][3] + b1, a1));
            }
        }
    } else {
        const int half = warp_n >> 1;                 // 0 = B, 1 = C
        #pragma unroll
        for (int mi = 0; mi < 4; mi++) {
            float s0 = 0.0f, s1 = 0.0f;
            #pragma unroll
            for (int ni = 0; ni < 4; ni++) {
                s0 += acc[mi][ni][0] * acc[mi][ni][0] + acc[mi][ni][1] * acc[mi][ni][1];
                s1 += acc[mi][ni][2] * acc[mi][ni][2] + acc[mi][ni][3] * acc[mi][ni][3];
            }
            s0 += __shfl_xor_sync(0xffffffffu, s0, 1);
            s0 += __shfl_xor_sync(0xffffffffu, s0, 2);
            s1 += __shfl_xor_sync(0xffffffffu, s1, 1);
            s1 += __shfl_xor_sync(0xffffffffu, s1, 2);
            if (tig == 0) {
                const int r = warp_m * 64 + mi * 16 + g;
                atomicAdd(&ssred[half * 128 + r], s0);
                atomicAdd(&ssred[half * 128 + r + 8], s1);
            }
        }
        __syncthreads();
        const float* gam = half ? gCn : gBn;
        float* outp = half ? Cm : Bm;
        #pragma unroll
        for (int mi = 0; mi < 4; mi++) {
            const int r = warp_m * 64 + mi * 16 + g;
            const float rs0 = rsqrtf(ssred[half * 128 + r] * (1.0f / 64.0f) + 1e-6f);
            const float rs1 = rsqrtf(ssred[half * 128 + r + 8] * (1.0f / 64.0f) + 1e-6f);
            #pragma unroll
            for (int ni = 0; ni < 4; ni++) {
                const int nl = (warp_n - half * 2) * 32 + ni * 8 + 2 * tig;  // 0..63
                const float g0 = gam[nl], g1 = gam[nl + 1];
                *(float2*)&outp[(size_t)(row0 + r) * 64 + nl] =
                    make_float2(acc[mi][ni][0] * rs0 * g0, acc[mi][ni][1] * rs0 * g1);
                *(float2*)&outp[(size_t)(row0 + r + 8) * 64 + nl] =
                    make_float2(acc[mi][ni][2] * rs1 * g0, acc[mi][ni][3] * rs1 * g1);
            }
        }
    }
}

// ============================ prep kernels ============================

__global__ void acoef_k(const float* __restrict__ A_log, float* __restrict__ Ac)
{
    int d = threadIdx.x;
    Ac[d] = -expf(fminf(fmaxf(A_log[d], -20.0f), 2.0f));
}

// [0,8192): round x -> xt (float4/thread). [8192,9280): weight transposes+cvt.
__global__ void __launch_bounds__(256)
prep_k(const float* __restrict__ x,
       const float* __restrict__ Wxp, const float* __restrict__ Wdt,
       const float* __restrict__ Wout, const float* __restrict__ WB,
       const float* __restrict__ WC,
       float* __restrict__ xt, float* __restrict__ Twxp, float* __restrict__ Twdt,
       float* __restrict__ Twout, float* __restrict__ Twbc)
{
    int bid = blockIdx.x;
    if (bid < 8192) {
        const int i = bid * 256 + threadIdx.x;
        float4 v = ((const float4*)x)[i];
        ((uint4*)xt)[i] = make_uint4(f2tf32(v.x), f2tf32(v.y), f2tf32(v.z), f2tf32(v.w));
        return;
    }
    bid -= 8192;
    const float* W; float* Wt; int N, lb;
    if (bid < 512)       { W = Wxp;  Wt = Twxp;            N = 1024; lb = bid; }
    else if (bid < 768)  { W = Wdt;  Wt = Twdt;            N = 512;  lb = bid - 512; }
    else if (bid < 1024) { W = Wout; Wt = Twout;           N = 512;  lb = bid - 768; }
    else if (bid < 1056) { W = WB;   Wt = Twbc;            N = 64;   lb = bid - 1024; }
    else                 { W = WC;   Wt = Twbc + 64 * 512; N = 64;   lb = bid - 1056; }
    const int tiles_n = N / 32;
    const int n0 = (lb % tiles_n) * 32;
    const int k0 = (lb / tiles_n) * 32;
    __shared__ float tile[32][33];
    const int tx = threadIdx.x & 31, ty = threadIdx.x >> 5;
    for (int i = ty; i < 32; i += 8)
        tile[i][tx] = W[(size_t)(k0 + i) * N + n0 + tx];
    __syncthreads();
    for (int i = ty; i < 32; i += 8)
        Wt[(size_t)(n0 + i) * 512 + k0 + tx] = __uint_as_float(f2tf32(tile[tx][i]));
}

// ============================ scan kernels ============================

// Intra-chunk recurrence (f32x2, prefetch). Y gets y_intra + D_skip*x_bar.
// Grid (NBLK, 2) x 256 threads: blockIdx.y selects channel half.
__global__ void __launch_bounds__(256)
scan_intra_k(const float* __restrict__ xp, const float* __restrict__ Bm,
             const float* __restrict__ Cm, const float* __restrict__ Dskip,
             float* __restrict__ ax, float* __restrict__ Y,
             float* __restrict__ cs, float* __restrict__ dtot)
{
    __shared__ float4 Bs[64][16];
    __shared__ float4 Cs[64][16];
    const int blk = blockIdx.x;
    const int d = blockIdx.y * 256 + threadIdx.x;
    const size_t l0 = (size_t)blk * 64;

    for (int t = threadIdx.x; t < 64 * 16; t += 256) {
        int r = t >> 4, c = t & 15;
        Bs[r][c] = ((const float4*)Bm)[(l0 + r) * 16 + c];
        Cs[r][c] = ((const float4*)Cm)[(l0 + r) * 16 + c];
    }
    __syncthreads();

    ull S2[32];
    #pragma unroll
    for (int q = 0; q < 32; q++) S2[q] = 0ull;
    float dec = 1.0f;
    const float dsk = Dskip[d];

    const float* axp = ax + l0 * 512 + d;
    const float* xpp = xp + l0 * 1024 + d;
    float av = axp[0];
    float xv = xpp[0];

    #pragma unroll 1
    for (int i = 0; i < 64; i++) {
        float av_n = 0.0f, xv_n = 0.0f;
        if (i < 63) { av_n = axp[(size_t)(i + 1) * 512]; xv_n = xpp[(size_t)(i + 1) * 1024]; }
        const size_t m = l0 + i;
        dec *= av;
        ax[m * 512 + d] = dec;
        const ull av2 = pack2(av, av);
        const ull xv2 = pack2(xv, xv);
        const ull* Bp = (const ull*)&Bs[i][0];
        const ull* Cp = (const ull*)&Cs[i][0];
        ull y2 = 0ull;
        #pragma unroll
        for (int q = 0; q < 32; q++) {
            ull bx; MUL2(bx, Bp[q], xv2);
            FMA2_ACC(bx, av2, S2[q]);   // bx = av*S + b*x
            S2[q] = bx;
            FMA2_ACC(y2, Cp[q], S2[q]);
        }
        float ylo, yhi; unpack2(y2, ylo, yhi);
        Y[m * 512 + d] = ylo + yhi + dsk * xv;
        av = av_n; xv = xv_n;
    }

    #pragma unroll
    for (int q = 0; q < 32; q++) {
        float slo, shi; unpack2(S2[q], slo, shi);
        cs[((size_t)blk * 64 + 2 * q) * 512 + d] = slo;
        cs[((size_t)blk * 64 + 2 * q + 1) * 512 + d] = shi;
    }
    dtot[(size_t)blk * 512 + d] = dec;
}

// Inter-chunk state scan (prefetch), float4 over d; cs -> prev_state in place.
__global__ void state_scan_k(float* __restrict__ cs, const float* __restrict__ dtot)
{
    const int idx = blockIdx.x * blockDim.x + threadIdx.x;   // B*N*128 = 32768
    const int d4 = idx & 127;
    const int n = (idx >> 7) & 63;
    const int b = idx >> 13;
    float4* cs4 = (float4*)cs;
    const float4* dt4 = (const float4*)dtot;
    float4 s = make_float4(0.f, 0.f, 0.f, 0.f);

    size_t off = ((size_t)(b * 64) * 64 + n) * 128 + d4;
    float4 v = cs4[off];
    float4 a = dt4[(size_t)(b * 64) * 128 + d4];

    #pragma unroll 1
    for (int ch = 0; ch < 64; ch++) {
        float4 vn, an;
        if (ch < 63) {
            const int blkn = b * 64 + ch + 1;
            vn = cs4[((size_t)blkn * 64 + n) * 128 + d4];
            an = dt4[(size_t)blkn * 128 + d4];
        } else { vn = s; an = s; }
        cs4[off] = s;
        s.x = fmaf(s.x, a.x, v.x);
        s.y = fmaf(s.y, a.y, v.y);
        s.z = fmaf(s.z, a.z, v.z);
        s.w = fmaf(s.w, a.w, v.w);
        off = ((size_t)(b * 64 + ch + 1) * 64 + n) * 128 + d4;
        v = vn; a = an;
    }
}

// y += decay * (C @ prev_state)   (f32x2; D_skip already folded in scan_intra)
// Grid (NBLK, 2) x 256 threads.
__global__ void __launch_bounds__(256)
yinter_k(const float* __restrict__ Cm, const float* __restrict__ ps,
         const float* __restrict__ decay, float* __restrict__ Y)
{
    __shared__ float4 Cs[64][16];
    const int blk = blockIdx.x;
    const int d = blockIdx.y * 256 + threadIdx.x;
    const size_t l0 = (size_t)blk * 64;

    for (int t = threadIdx.x; t < 64 * 16; t += 256) {
        int r = t >> 4, c = t & 15;
        Cs[r][c] = ((const float4*)Cm)[(l0 + r) * 16 + c];
    }
    __syncthreads();

    ull PS2[32];
    #pragma unroll
    for (int q = 0; q < 32; q++)
        PS2[q] = pack2(ps[((size_t)blk * 64 + 2 * q) * 512 + d],
                       ps[((size_t)blk * 64 + 2 * q + 1) * 512 + d]);

    float dc = decay[l0 * 512 + d];
    float yv = Y[l0 * 512 + d];

    #pragma unroll 1
    for (int i = 0; i < 64; i++) {
        float dc_n = 0.0f, yv_n = 0.0f;
        if (i < 63) {
            dc_n = decay[(l0 + i + 1) * 512 + d];
            yv_n = Y[(l0 + i + 1) * 512 + d];
        }
        const ull* Cp = (const ull*)&Cs[i][0];
        ull y2 = 0ull;
        #pragma unroll
        for (int q = 0; q < 32; q++)
            FMA2_ACC(y2, Cp[q], PS2[q]);
        float ylo, yhi; unpack2(y2, ylo, yhi);
        Y[(l0 + i) * 512 + d] = yv + dc * (ylo + yhi);
        dc = dc_n; yv = yv_n;
    }
}

// h = tf32round(rmsnorm(y, g) * silu(z)), in place over Y.
__global__ void outnorm_k(float* __restrict__ Y, const float* __restrict__ xp,
                          const float* __restrict__ g)
{
    __shared__ float red[256];
    const int m = blockIdx.x;
    const int t = threadIdx.x;
    float v0 = Y[(size_t)m * 512 + t];
    float v1 = Y[(size_t)m * 512 + t + 256];
    red[t] = v0 * v0 + v1 * v1;
    __syncthreads();
    for (int s = 128; s > 0; s >>= 1) {
        if (t < s) red[t] += red[t + s];
        __syncthreads();
    }
    float rs = rsqrtf(red[0] * (1.0f / 512.0f) + 1e-6f);
    float z0 = xp[(size_t)m * 1024 + 512 + t];
    float z1 = xp[(size_t)m * 1024 + 512 + t + 256];
    float s0 = z0 / (1.0f + expf(-z0));
    float s1 = z1 / (1.0f + expf(-z1));
    Y[(size_t)m * 512 + t]       = __uint_as_float(f2tf32(v0 * rs * g[t] * s0));
    Y[(size_t)m * 512 + t + 256] = __uint_as_float(f2tf32(v1 * rs * g[t + 256] * s1));
}

// ============================ launch ============================
#define GEMM_SMEM (NSTG * STG_F * 4 * 2)   // 110592 bytes

extern "C" void kernel_launch(void* const* d_in, const int* in_sizes, int n_in,
                              void* d_out, int out_size)
{
    const float* x       = (const float*)d_in[0];
    const float* A_log   = (const float*)d_in[1];
    const float* dt_bias = (const float*)d_in[2];
    const float* D_skip  = (const float*)d_in[3];
    const float* W_xproj = (const float*)d_in[4];
    const float* b_xproj = (const float*)d_in[5];
    const float* W_B     = (const float*)d_in[6];
    const float* W_C     = (const float*)d_in[7];
    const float* W_dt    = (const float*)d_in[8];
    const float* g_Bn    = (const float*)d_in[9];
    const float* g_Cn    = (const float*)d_in[10];
    const float* g_on    = (const float*)d_in[11];
    const float* W_out   = (const float*)d_in[12];
    const float* b_out   = (const float*)d_in[13];
    float* out = (float*)d_out;

    float *p_xp, *p_xt, *p_xbt, *p_Bm, *p_Cm, *p_ax, *p_Y, *p_cs, *p_dt, *p_Ac;
    float *p_Wxp, *p_Wdt, *p_Wout, *p_Wbc;
    cudaGetSymbolAddress((void**)&p_xp,  g_xp);
    cudaGetSymbolAddress((void**)&p_xt,  g_xt);
    cudaGetSymbolAddress((void**)&p_xbt, g_xbt);
    cudaGetSymbolAddress((void**)&p_Bm,  g_Bm);
    cudaGetSymbolAddress((void**)&p_Cm,  g_Cm);
    cudaGetSymbolAddress((void**)&p_ax,  g_ax);
    cudaGetSymbolAddress((void**)&p_Y,   g_Yb);
    cudaGetSymbolAddress((void**)&p_cs,  g_cs);
    cudaGetSymbolAddress((void**)&p_dt,  g_dtot);
    cudaGetSymbolAddress((void**)&p_Ac,  g_Ac);
    cudaGetSymbolAddress((void**)&p_Wxp,  g_Wt_xp);
    cudaGetSymbolAddress((void**)&p_Wdt,  g_Wt_dt);
    cudaGetSymbolAddress((void**)&p_Wout, g_Wt_out);
    cudaGetSymbolAddress((void**)&p_Wbc,  g_Wt_bc);

    cudaFuncSetAttribute(mma_gemm_k<0>, cudaFuncAttributeMaxDynamicSharedMemorySize, GEMM_SMEM);
    cudaFuncSetAttribute(mma_gemm_k<3>, cudaFuncAttributeMaxDynamicSharedMemorySize, GEMM_SMEM);
    cudaFuncSetAttribute(dtbc_gemm_k,   cudaFuncAttributeMaxDynamicSharedMemorySize, GEMM_SMEM);

    // 0: A coefficient
    acoef_k<<<1, 512>>>(A_log, p_Ac);
    // 1: weight transposes + x rounding
    prep_k<<<9280, 256>>>(x, W_xproj, W_dt, W_out, W_B, W_C,
                          p_xt, p_Wxp, p_Wdt, p_Wout, p_Wbc);
    // 2: xp = x @ W_xproj + b_xproj (also emits tf32-rounded x_bar)
    mma_gemm_k<3><<<dim3(8, 128), 256, GEMM_SMEM>>>(
        p_xt, 512, p_Wxp, b_xproj, p_xp, p_xbt, 1024);
    // 3: merged dt-GEMM + fused B|C projection + rmsnorm (one wave)
    dtbc_gemm_k<<<dim3(5, 128), 256, GEMM_SMEM>>>(
        p_xbt, p_Wdt, p_Wbc, dt_bias, p_Ac, p_ax, p_Bm, p_Cm, g_Bn, g_Cn);
    // 4: intra-chunk recurrence (+ D_skip*x_bar folded), split channels
    scan_intra_k<<<dim3(NBLK, 2), 256>>>(p_xp, p_Bm, p_Cm, D_skip, p_ax, p_Y, p_cs, p_dt);
    // 5: inter-chunk state scan
    state_scan_k<<<(BQ * NQ * 128) / 256, 256>>>(p_cs, p_dt);
    // 6: y += decay * (C @ prev_state), split channels
    yinter_k<<<dim3(NBLK, 2), 256>>>(p_Cm, p_cs, p_ax, p_Y);
    // 7: h = rmsnorm(y) * silu(z) (tf32)
    outnorm_k<<<MQ, 256>>>(p_Y, p_xp, g_on);
    // 8: out = h @ W_out + b_out
    mma_gemm_k<0><<<dim3(4, 128), 256, GEMM_SMEM>>>(
        p_Y, 512, p_Wout, b_out, out, nullptr, 512);
}

// round 10
// speedup vs baseline: 1.0592x; 1.0592x over previous
#include <cuda_runtime.h>
#include <math.h>
#include <stdint.h>

// Problem constants (fixed shapes)
#define BQ 4
#define LQ 4096
#define DQ 512
#define NQ 64
#define MQ (BQ * LQ)        // 16384 rows
#define NBLK 256            // (b,chunk) blocks, chunk=64

typedef unsigned long long ull;

// -------- scratch (device globals; no allocation allowed) --------
__device__ float g_z[(size_t)MQ * 512];          // z half of xproj (ld 512)
__device__ float g_xt[(size_t)MQ * 512];         // tf32-rounded x
__device__ float g_xbt[(size_t)MQ * 512];        // tf32-rounded x_bar
__device__ float g_Bm[(size_t)MQ * 64];          // B proj (rmsnormed)
__device__ float g_Cm[(size_t)MQ * 64];          // C proj (rmsnormed)
__device__ float g_ax[(size_t)MQ * 512];         // a=exp(la); overwritten w/ cumulative decay
__device__ float g_Yb[(size_t)MQ * 512];         // y buffer (h stored tf32-rounded)
__device__ float g_cs[(size_t)NBLK * 64 * 512];  // chunk states -> prev states
__device__ float g_dtot[(size_t)NBLK * 512];     // per-chunk total decay
__device__ float g_Ac[512];                      // A coefficient
// transposed tf32 weights: Wt[n][k], k contiguous (512)
__device__ float g_Wt_xp[1024 * 512];
__device__ float g_Wt_dt[512 * 512];
__device__ float g_Wt_out[512 * 512];
__device__ float g_Wt_bc[128 * 512];             // rows 0..63 = W_B^T, 64..127 = W_C^T

// ============================ helpers ============================
__device__ __forceinline__ uint32_t f2tf32(float x) {
    uint32_t u;
    asm("cvt.rna.tf32.f32 %0, %1;" : "=r"(u) : "f"(x));
    return u;
}
__device__ __forceinline__ void mma_tf32(float* d, const uint32_t* a, const uint32_t* b) {
    asm volatile(
        "mma.sync.aligned.m16n8k8.row.col.f32.tf32.tf32.f32 "
        "{%0,%1,%2,%3}, {%4,%5,%6,%7}, {%8,%9}, {%0,%1,%2,%3};"
        : "+f"(d[0]), "+f"(d[1]), "+f"(d[2]), "+f"(d[3])
        : "r"(a[0]), "r"(a[1]), "r"(a[2]), "r"(a[3]), "r"(b[0]), "r"(b[1]));
}
__device__ __forceinline__ float dt_transform(float v, float Acoef) {
    float sp  = (v > 20.0f) ? v : log1pf(expf(v));
    float dtv = fminf(fmaxf(sp, 1e-4f), 5.0f);
    float la  = fminf(fmaxf(dtv * Acoef, -18.4206807f), 0.0f);
    return expf(la);
}
__device__ __forceinline__ void cpasync16(uint32_t saddr, const void* g) {
    asm volatile("cp.async.cg.shared.global [%0], [%1], 16;" :: "r"(saddr), "l"(g));
}
#define CP_COMMIT() asm volatile("cp.async.commit_group;" ::: "memory")
#define CP_WAIT1()  asm volatile("cp.async.wait_group 1;" ::: "memory")
#define CP_WAIT0()  asm volatile("cp.async.wait_group 0;" ::: "memory")

__device__ __forceinline__ ull pack2(float lo, float hi) {
    ull r; asm("mov.b64 %0, {%1, %2};" : "=l"(r) : "f"(lo), "f"(hi)); return r;
}
__device__ __forceinline__ void unpack2(ull v, float& lo, float& hi) {
    asm("mov.b64 {%0, %1}, %2;" : "=f"(lo), "=f"(hi) : "l"(v));
}
#define FMA2_ACC(d, a, b) \
    asm("fma.rn.f32x2 %0, %1, %2, %0;" : "+l"(d) : "l"(a), "l"(b))
#define MUL2(d, a, b) \
    asm("mul.rn.f32x2 %0, %1, %2;" : "=l"(d) : "l"(a), "l"(b))

// ============================ GEMM mainloop (3-stage, 1 barrier/chunk) ============
// D[128,128] tile = A[row0..+128, 0..512)(lda) * Bt[col0..+128, 0..512)^T.
// 8 warps (2 M x 4 N), warp tile 64x32, m16n8k8, scalar 32-bit LDS fragments.
#define STG_F (128 * 36)
#define NSTG 3

__device__ __forceinline__ void gemm_mainloop(
    const float* __restrict__ A, int lda, const float* __restrict__ Bt,
    int row0, int col0, float* sm, float acc[4][4][4],
    int tid, int warp_m, int warp_n, int g, int tig)
{
    float* Asm = sm;                 // NSTG stages x 128x36
    float* Bsm = sm + NSTG * STG_F;
    const uint32_t asm_u = (uint32_t)__cvta_generic_to_shared(Asm);
    const uint32_t bsm_u = (uint32_t)__cvta_generic_to_shared(Bsm);
    const int ldm = tid >> 3;
    const int ldk4 = tid & 7;

    auto issue = [&](int s, int k0) {
        #pragma unroll
        for (int j = 0; j < 4; j++) {
            const int m = ldm + 32 * j;
            const uint32_t off = (uint32_t)((s * STG_F + m * 36 + ldk4 * 4) * 4);
            cpasync16(asm_u + off, &A[(size_t)(row0 + m) * lda + k0 + ldk4 * 4]);
            cpasync16(bsm_u + off, &Bt[(size_t)(col0 + m) * 512 + k0 + ldk4 * 4]);
        }
        CP_COMMIT();
    };
    issue(0, 0);
    issue(1, 32);

    #pragma unroll 1
    for (int c = 0; c < 16; c++) {
        const int s = c % NSTG;
        if (c < 15) { CP_WAIT1(); } else { CP_WAIT0(); }
        __syncthreads();
        if (c + 2 < 16) issue((c + 2) % NSTG, (c + 2) * 32);
        const uint32_t* AsU = (const uint32_t*)(Asm + s * STG_F);
        const uint32_t* BsU = (const uint32_t*)(Bsm + s * STG_F);
        #pragma unroll
        for (int kk = 0; kk < 4; kk++) {
            const int k = kk * 8;
            uint32_t af[4][4];
            #pragma unroll
            for (int mi = 0; mi < 4; mi++) {
                const int mr = warp_m * 64 + mi * 16 + g;
                af[mi][0] = AsU[mr * 36 + k + tig];
                af[mi][1] = AsU[(mr + 8) * 36 + k + tig];
                af[mi][2] = AsU[mr * 36 + k + tig + 4];
                af[mi][3] = AsU[(mr + 8) * 36 + k + tig + 4];
            }
            #pragma unroll
            for (int ni = 0; ni < 4; ni++) {
                uint32_t bf[2];
                const int nr = warp_n * 32 + ni * 8 + g;
                bf[0] = BsU[nr * 36 + k + tig];
                bf[1] = BsU[nr * 36 + k + tig + 4];
                #pragma unroll
                for (int mi = 0; mi < 4; mi++)
                    mma_tf32(acc[mi][ni], af[mi], bf);
            }
        }
    }
    __syncthreads();
}

// ---- EPI 0: +bias -> out0 (ldc).
// ---- EPI 3: xproj: +bias; n<512 -> tf32-rounded x_bar to out1 (ld 512);
//             n>=512 -> z to out0 (ld 512, col n-512).
template <int EPI>
__global__ void __launch_bounds__(256, 2)
mma_gemm_k(const float* __restrict__ A, int lda,
           const float* __restrict__ Bt,
           const float* __restrict__ bias,
           float* __restrict__ out0, float* __restrict__ out1, int ldc)
{
    extern __shared__ float sm[];
    const int tid = threadIdx.x;
    const int wid = tid >> 5;
    const int lane = tid & 31;
    const int g = lane >> 2;
    const int tig = lane & 3;
    const int warp_m = wid >> 2;
    const int warp_n = wid & 3;
    const int row0 = blockIdx.y * 128;
    const int col0 = blockIdx.x * 128;

    float acc[4][4][4] = {};
    gemm_mainloop(A, lda, Bt, row0, col0, sm, acc, tid, warp_m, warp_n, g, tig);

    #pragma unroll
    for (int mi = 0; mi < 4; mi++) {
        const int m = row0 + warp_m * 64 + mi * 16 + g;
        #pragma unroll
        for (int ni = 0; ni < 4; ni++) {
            const int n = col0 + warp_n * 32 + ni * 8 + 2 * tig;
            float d0 = acc[mi][ni][0], d1 = acc[mi][ni][1];
            float d2 = acc[mi][ni][2], d3 = acc[mi][ni][3];
            const float b0 = bias[n], b1 = bias[n + 1];
            d0 += b0; d1 += b1; d2 += b0; d3 += b1;
            if (EPI == 3) {
                if (n < 512) {
                    *(float2*)&out1[(size_t)m * 512 + n] = make_float2(
                        __uint_as_float(f2tf32(d0)), __uint_as_float(f2tf32(d1)));
                    *(float2*)&out1[(size_t)(m + 8) * 512 + n] = make_float2(
                        __uint_as_float(f2tf32(d2)), __uint_as_float(f2tf32(d3)));
                } else {
                    *(float2*)&out0[(size_t)m * 512 + n - 512] = make_float2(d0, d1);
                    *(float2*)&out0[(size_t)(m + 8) * 512 + n - 512] = make_float2(d2, d3);
                }
            } else {
                *(float2*)&out0[(size_t)m * ldc + n] = make_float2(d0, d1);
                *(float2*)&out0[(size_t)(m + 8) * ldc + n] = make_float2(d2, d3);
            }
        }
    }
}

// ---- merged dt (blockIdx.x<4) + fused B|C rmsnorm (blockIdx.x==4) ----
__global__ void __launch_bounds__(256, 2)
dtbc_gemm_k(const float* __restrict__ xbt,
            const float* __restrict__ Wdt, const float* __restrict__ Wbc,
            const float* __restrict__ dt_bias, const float* __restrict__ Ac,
            float* __restrict__ ax,
            float* __restrict__ Bm, float* __restrict__ Cm,
            const float* __restrict__ gBn, const float* __restrict__ gCn)
{
    extern __shared__ float sm[];
    __shared__ float ssred[256];
    const int tid = threadIdx.x;
    const int wid = tid >> 5;
    const int lane = tid & 31;
    const int g = lane >> 2;
    const int tig = lane & 3;
    const int warp_m = wid >> 2;
    const int warp_n = wid & 3;
    const int row0 = blockIdx.y * 128;
    const bool is_dt = blockIdx.x < 4;
    const int col0 = is_dt ? blockIdx.x * 128 : 0;
    const float* Bt = is_dt ? Wdt : Wbc;

    if (!is_dt) ssred[tid] = 0.0f;

    float acc[4][4][4] = {};
    gemm_mainloop(xbt, 512, Bt, row0, col0, sm, acc, tid, warp_m, warp_n, g, tig);

    if (is_dt) {
        #pragma unroll
        for (int mi = 0; mi < 4; mi++) {
            const int m = row0 + warp_m * 64 + mi * 16 + g;
            #pragma unroll
            for (int ni = 0; ni < 4; ni++) {
                const int n = col0 + warp_n * 32 + ni * 8 + 2 * tig;
                const float b0 = dt_bias[n], b1 = dt_bias[n + 1];
                const float a0 = Ac[n], a1 = Ac[n + 1];
                *(float2*)&ax[(size_t)m * 512 + n] = make_float2(
                    dt_transform(acc[mi][ni][0] + b0, a0),
                    dt_transform(acc[mi][ni][1] + b1, a1));
                *(float2*)&ax[(size_t)(m + 8) * 512 + n] = make_float2(
                    dt_transform(acc[mi][ni][2] + b0, a0),
                    dt_transform(acc[mi][ni][3] + b1, a1));
            }
        }
    } else {
        const int half = warp_n >> 1;                 // 0 = B, 1 = C
        #pragma unroll
        for (int mi = 0; mi < 4; mi++) {
            float s0 = 0.0f, s1 = 0.0f;
            #pragma unroll
            for (int ni = 0; ni < 4; ni++) {
                s0 += acc[mi][ni][0] * acc[mi][ni][0] + acc[mi][ni][1] * acc[mi][ni][1];
                s1 += acc[mi][ni][2] * acc[mi][ni][2] + acc[mi][ni][3] * acc[mi][ni][3];
            }
            s0 += __shfl_xor_sync(0xffffffffu, s0, 1);
            s0 += __shfl_xor_sync(0xffffffffu, s0, 2);
            s1 += __shfl_xor_sync(0xffffffffu, s1, 1);
            s1 += __shfl_xor_sync(0xffffffffu, s1, 2);
            if (tig == 0) {
                const int r = warp_m * 64 + mi * 16 + g;
                atomicAdd(&ssred[half * 128 + r], s0);
                atomicAdd(&ssred[half * 128 + r + 8], s1);
            }
        }
        __syncthreads();
        const float* gam = half ? gCn : gBn;
        float* outp = half ? Cm : Bm;
        #pragma unroll
        for (int mi = 0; mi < 4; mi++) {
            const int r = warp_m * 64 + mi * 16 + g;
            const float rs0 = rsqrtf(ssred[half * 128 + r] * (1.0f / 64.0f) + 1e-6f);
            const float rs1 = rsqrtf(ssred[half * 128 + r + 8] * (1.0f / 64.0f) + 1e-6f);
            #pragma unroll
            for (int ni = 0; ni < 4; ni++) {
                const int nl = (warp_n - half * 2) * 32 + ni * 8 + 2 * tig;  // 0..63
                const float g0 = gam[nl], g1 = gam[nl + 1];
                *(float2*)&outp[(size_t)(row0 + r) * 64 + nl] =
                    make_float2(acc[mi][ni][0] * rs0 * g0, acc[mi][ni][1] * rs0 * g1);
                *(float2*)&outp[(size_t)(row0 + r + 8) * 64 + nl] =
                    make_float2(acc[mi][ni][2] * rs1 * g0, acc[mi][ni][3] * rs1 * g1);
            }
        }
    }
}

// ============================ prep kernels ============================

__global__ void acoef_k(const float* __restrict__ A_log, float* __restrict__ Ac)
{
    int d = threadIdx.x;
    Ac[d] = -expf(fminf(fmaxf(A_log[d], -20.0f), 2.0f));
}

// [0,8192): round x -> xt (float4/thread). [8192,9280): weight transposes+cvt.
__global__ void __launch_bounds__(256)
prep_k(const float* __restrict__ x,
       const float* __restrict__ Wxp, const float* __restrict__ Wdt,
       const float* __restrict__ Wout, const float* __restrict__ WB,
       const float* __restrict__ WC,
       float* __restrict__ xt, float* __restrict__ Twxp, float* __restrict__ Twdt,
       float* __restrict__ Twout, float* __restrict__ Twbc)
{
    int bid = blockIdx.x;
    if (bid < 8192) {
        const int i = bid * 256 + threadIdx.x;
        float4 v = ((const float4*)x)[i];
        ((uint4*)xt)[i] = make_uint4(f2tf32(v.x), f2tf32(v.y), f2tf32(v.z), f2tf32(v.w));
        return;
    }
    bid -= 8192;
    const float* W; float* Wt; int N, lb;
    if (bid < 512)       { W = Wxp;  Wt = Twxp;            N = 1024; lb = bid; }
    else if (bid < 768)  { W = Wdt;  Wt = Twdt;            N = 512;  lb = bid - 512; }
    else if (bid < 1024) { W = Wout; Wt = Twout;           N = 512;  lb = bid - 768; }
    else if (bid < 1056) { W = WB;   Wt = Twbc;            N = 64;   lb = bid - 1024; }
    else                 { W = WC;   Wt = Twbc + 64 * 512; N = 64;   lb = bid - 1056; }
    const int tiles_n = N / 32;
    const int n0 = (lb % tiles_n) * 32;
    const int k0 = (lb / tiles_n) * 32;
    __shared__ float tile[32][33];
    const int tx = threadIdx.x & 31, ty = threadIdx.x >> 5;
    for (int i = ty; i < 32; i += 8)
        tile[i][tx] = W[(size_t)(k0 + i) * N + n0 + tx];
    __syncthreads();
    for (int i = ty; i < 32; i += 8)
        Wt[(size_t)(n0 + i) * 512 + k0 + tx] = __uint_as_float(f2tf32(tile[tx][i]));
}

// ============================ scan kernels ============================

// Intra-chunk recurrence (f32x2, prefetch). Y gets y_intra + D_skip*x_bar.
// x_bar read from tf32-rounded xbt (ld 512).
__global__ void __launch_bounds__(512)
scan_intra_k(const float* __restrict__ xbt, const float* __restrict__ Bm,
             const float* __restrict__ Cm, const float* __restrict__ Dskip,
             float* __restrict__ ax, float* __restrict__ Y,
             float* __restrict__ cs, float* __restrict__ dtot)
{
    __shared__ float4 Bs[64][16];
    __shared__ float4 Cs[64][16];
    const int blk = blockIdx.x;
    const int d = threadIdx.x;
    const size_t l0 = (size_t)blk * 64;

    for (int t = d; t < 64 * 16; t += 512) {
        int r = t >> 4, c = t & 15;
        Bs[r][c] = ((const float4*)Bm)[(l0 + r) * 16 + c];
        Cs[r][c] = ((const float4*)Cm)[(l0 + r) * 16 + c];
    }
    __syncthreads();

    ull S2[32];
    #pragma unroll
    for (int q = 0; q < 32; q++) S2[q] = 0ull;
    float dec = 1.0f;
    const float dsk = Dskip[d];

    const float* axp = ax + l0 * 512 + d;
    const float* xpp = xbt + l0 * 512 + d;
    float av = axp[0];
    float xv = xpp[0];

    #pragma unroll 1
    for (int i = 0; i < 64; i++) {
        float av_n = 0.0f, xv_n = 0.0f;
        if (i < 63) { av_n = axp[(size_t)(i + 1) * 512]; xv_n = xpp[(size_t)(i + 1) * 512]; }
        const size_t m = l0 + i;
        dec *= av;
        ax[m * 512 + d] = dec;
        const ull av2 = pack2(av, av);
        const ull xv2 = pack2(xv, xv);
        const ull* Bp = (const ull*)&Bs[i][0];
        const ull* Cp = (const ull*)&Cs[i][0];
        ull y2 = 0ull;
        #pragma unroll
        for (int q = 0; q < 32; q++) {
            ull bx; MUL2(bx, Bp[q], xv2);
            FMA2_ACC(bx, av2, S2[q]);   // bx = av*S + b*x
            S2[q] = bx;
            FMA2_ACC(y2, Cp[q], S2[q]);
        }
        float ylo, yhi; unpack2(y2, ylo, yhi);
        Y[m * 512 + d] = ylo + yhi + dsk * xv;
        av = av_n; xv = xv_n;
    }

    #pragma unroll
    for (int q = 0; q < 32; q++) {
        float slo, shi; unpack2(S2[q], slo, shi);
        cs[((size_t)blk * 64 + 2 * q) * 512 + d] = slo;
        cs[((size_t)blk * 64 + 2 * q + 1) * 512 + d] = shi;
    }
    dtot[(size_t)blk * 512 + d] = dec;
}

// Inter-chunk state scan (prefetch), float4 over d; cs -> prev_state in place.
__global__ void state_scan_k(float* __restrict__ cs, const float* __restrict__ dtot)
{
    const int idx = blockIdx.x * blockDim.x + threadIdx.x;   // B*N*128 = 32768
    const int d4 = idx & 127;
    const int n = (idx >> 7) & 63;
    const int b = idx >> 13;
    float4* cs4 = (float4*)cs;
    const float4* dt4 = (const float4*)dtot;
    float4 s = make_float4(0.f, 0.f, 0.f, 0.f);

    size_t off = ((size_t)(b * 64) * 64 + n) * 128 + d4;
    float4 v = cs4[off];
    float4 a = dt4[(size_t)(b * 64) * 128 + d4];

    #pragma unroll 1
    for (int ch = 0; ch < 64; ch++) {
        float4 vn, an;
        if (ch < 63) {
            const int blkn = b * 64 + ch + 1;
            vn = cs4[((size_t)blkn * 64 + n) * 128 + d4];
            an = dt4[(size_t)blkn * 128 + d4];
        } else { vn = s; an = s; }
        cs4[off] = s;
        s.x = fmaf(s.x, a.x, v.x);
        s.y = fmaf(s.y, a.y, v.y);
        s.z = fmaf(s.z, a.z, v.z);
        s.w = fmaf(s.w, a.w, v.w);
        off = ((size_t)(b * 64 + ch + 1) * 64 + n) * 128 + d4;
        v = vn; a = an;
    }
}

// y += decay * (C @ prev_state)   (f32x2; D_skip already folded in scan_intra)
__global__ void __launch_bounds__(512)
yinter_k(const float* __restrict__ Cm, const float* __restrict__ ps,
         const float* __restrict__ decay, float* __restrict__ Y)
{
    __shared__ float4 Cs[64][16];
    const int blk = blockIdx.x;
    const int d = threadIdx.x;
    const size_t l0 = (size_t)blk * 64;

    for (int t = d; t < 64 * 16; t += 512) {
        int r = t >> 4, c = t & 15;
        Cs[r][c] = ((const float4*)Cm)[(l0 + r) * 16 + c];
    }
    __syncthreads();

    ull PS2[32];
    #pragma unroll
    for (int q = 0; q < 32; q++)
        PS2[q] = pack2(ps[((size_t)blk * 64 + 2 * q) * 512 + d],
                       ps[((size_t)blk * 64 + 2 * q + 1) * 512 + d]);

    float dc = decay[l0 * 512 + d];
    float yv = Y[l0 * 512 + d];

    #pragma unroll 1
    for (int i = 0; i < 64; i++) {
        float dc_n = 0.0f, yv_n = 0.0f;
        if (i < 63) {
            dc_n = decay[(l0 + i + 1) * 512 + d];
            yv_n = Y[(l0 + i + 1) * 512 + d];
        }
        const ull* Cp = (const ull*)&Cs[i][0];
        ull y2 = 0ull;
        #pragma unroll
        for (int q = 0; q < 32; q++)
            FMA2_ACC(y2, Cp[q], PS2[q]);
        float ylo, yhi; unpack2(y2, ylo, yhi);
        Y[(l0 + i) * 512 + d] = yv + dc * (ylo + yhi);
        dc = dc_n; yv = yv_n;
    }
}

// h = tf32round(rmsnorm(y, g) * silu(z)), in place over Y; z from zbuf (ld 512).
__global__ void outnorm_k(float* __restrict__ Y, const float* __restrict__ zb,
                          const float* __restrict__ g)
{
    __shared__ float red[256];
    const int m = blockIdx.x;
    const int t = threadIdx.x;
    float v0 = Y[(size_t)m * 512 + t];
    float v1 = Y[(size_t)m * 512 + t + 256];
    red[t] = v0 * v0 + v1 * v1;
    __syncthreads();
    for (int s = 128; s > 0; s >>= 1) {
        if (t < s) red[t] += red[t + s];
        __syncthreads();
    }
    float rs = rsqrtf(red[0] * (1.0f / 512.0f) + 1e-6f);
    float z0 = zb[(size_t)m * 512 + t];
    float z1 = zb[(size_t)m * 512 + t + 256];
    float s0 = z0 / (1.0f + expf(-z0));
    float s1 = z1 / (1.0f + expf(-z1));
    Y[(size_t)m * 512 + t]       = __uint_as_float(f2tf32(v0 * rs * g[t] * s0));
    Y[(size_t)m * 512 + t + 256] = __uint_as_float(f2tf32(v1 * rs * g[t + 256] * s1));
}

// ============================ launch ============================
#define GEMM_SMEM (NSTG * STG_F * 4 * 2)   // 110592 bytes

extern "C" void kernel_launch(void* const* d_in, const int* in_sizes, int n_in,
                              void* d_out, int out_size)
{
    const float* x       = (const float*)d_in[0];
    const float* A_log   = (const float*)d_in[1];
    const float* dt_bias = (const float*)d_in[2];
    const float* D_skip  = (const float*)d_in[3];
    const float* W_xproj = (const float*)d_in[4];
    const float* b_xproj = (const float*)d_in[5];
    const float* W_B     = (const float*)d_in[6];
    const float* W_C     = (const float*)d_in[7];
    const float* W_dt    = (const float*)d_in[8];
    const float* g_Bn    = (const float*)d_in[9];
    const float* g_Cn    = (const float*)d_in[10];
    const float* g_on    = (const float*)d_in[11];
    const float* W_out   = (const float*)d_in[12];
    const float* b_out   = (const float*)d_in[13];
    float* out = (float*)d_out;

    float *p_z, *p_xt, *p_xbt, *p_Bm, *p_Cm, *p_ax, *p_Y, *p_cs, *p_dt, *p_Ac;
    float *p_Wxp, *p_Wdt, *p_Wout, *p_Wbc;
    cudaGetSymbolAddress((void**)&p_z,   g_z);
    cudaGetSymbolAddress((void**)&p_xt,  g_xt);
    cudaGetSymbolAddress((void**)&p_xbt, g_xbt);
    cudaGetSymbolAddress((void**)&p_Bm,  g_Bm);
    cudaGetSymbolAddress((void**)&p_Cm,  g_Cm);
    cudaGetSymbolAddress((void**)&p_ax,  g_ax);
    cudaGetSymbolAddress((void**)&p_Y,   g_Yb);
    cudaGetSymbolAddress((void**)&p_cs,  g_cs);
    cudaGetSymbolAddress((void**)&p_dt,  g_dtot);
    cudaGetSymbolAddress((void**)&p_Ac,  g_Ac);
    cudaGetSymbolAddress((void**)&p_Wxp,  g_Wt_xp);
    cudaGetSymbolAddress((void**)&p_Wdt,  g_Wt_dt);
    cudaGetSymbolAddress((void**)&p_Wout, g_Wt_out);
    cudaGetSymbolAddress((void**)&p_Wbc,  g_Wt_bc);

    cudaFuncSetAttribute(mma_gemm_k<0>, cudaFuncAttributeMaxDynamicSharedMemorySize, GEMM_SMEM);
    cudaFuncSetAttribute(mma_gemm_k<3>, cudaFuncAttributeMaxDynamicSharedMemorySize, GEMM_SMEM);
    cudaFuncSetAttribute(dtbc_gemm_k,   cudaFuncAttributeMaxDynamicSharedMemorySize, GEMM_SMEM);

    // 0: A coefficient
    acoef_k<<<1, 512>>>(A_log, p_Ac);
    // 1: weight transposes + x rounding
    prep_k<<<9280, 256>>>(x, W_xproj, W_dt, W_out, W_B, W_C,
                          p_xt, p_Wxp, p_Wdt, p_Wout, p_Wbc);
    // 2: xproj: z -> p_z, tf32 x_bar -> p_xbt
    mma_gemm_k<3><<<dim3(8, 128), 256, GEMM_SMEM>>>(
        p_xt, 512, p_Wxp, b_xproj, p_z, p_xbt, 512);
    // 3: merged dt-GEMM + fused B|C projection + rmsnorm (one wave)
    dtbc_gemm_k<<<dim3(5, 128), 256, GEMM_SMEM>>>(
        p_xbt, p_Wdt, p_Wbc, dt_bias, p_Ac, p_ax, p_Bm, p_Cm, g_Bn, g_Cn);
    // 4: intra-chunk recurrence (+ D_skip*x_bar folded)
    scan_intra_k<<<NBLK, 512>>>(p_xbt, p_Bm, p_Cm, D_skip, p_ax, p_Y, p_cs, p_dt);
    // 5: inter-chunk state scan
    state_scan_k<<<(BQ * NQ * 128) / 256, 256>>>(p_cs, p_dt);
    // 6: y += decay * (C @ prev_state)
    yinter_k<<<NBLK, 512>>>(p_Cm, p_cs, p_ax, p_Y);
    // 7: h = rmsnorm(y) * silu(z) (tf32)
    outnorm_k<<<MQ, 256>>>(p_Y, p_z, g_on);
    // 8: out = h @ W_out + b_out
    mma_gemm_k<0><<<dim3(4, 128), 256, GEMM_SMEM>>>(
        p_Y, 512, p_Wout, b_out, out, nullptr, 512);
}

// round 11
// speedup vs baseline: 1.3770x; 1.3000x over previous
#include <cuda_runtime.h>
#include <cuda_fp16.h>
#include <math.h>
#include <stdint.h>

// Problem constants (fixed shapes)
#define BQ 4
#define LQ 4096
#define DQ 512
#define NQ 64
#define MQ (BQ * LQ)        // 16384 rows
#define NBLK 256            // (b,chunk) blocks, chunk=64

typedef unsigned long long ull;

// -------- scratch (device globals; no allocation allowed) --------
__device__ float  g_z[(size_t)MQ * 512];          // z half of xproj (ld 512)
__device__ __half g_xt[(size_t)MQ * 512];         // fp16 x
__device__ __half g_xbt[(size_t)MQ * 512];        // fp16 x_bar
__device__ __half g_h[(size_t)MQ * 512];          // fp16 h (outnorm output)
__device__ float  g_Bm[(size_t)MQ * 64];          // B proj (rmsnormed)
__device__ float  g_Cm[(size_t)MQ * 64];          // C proj (rmsnormed)
__device__ float  g_ax[(size_t)MQ * 512];         // a=exp(la) -> cumulative decay
__device__ float  g_Yb[(size_t)MQ * 512];         // y buffer (fp32)
__device__ float  g_cs[(size_t)NBLK * 64 * 512];  // chunk states -> prev states
__device__ float  g_dtot[(size_t)NBLK * 512];     // per-chunk total decay
__device__ float  g_Ac[512];                      // A coefficient
// transposed fp16 weights: Wt[n][k], k contiguous (512)
__device__ __half g_Wt_xp[1024 * 512];
__device__ __half g_Wt_dt[512 * 512];
__device__ __half g_Wt_out[512 * 512];
__device__ __half g_Wt_bc[128 * 512];             // rows 0..63 = W_B^T, 64..127 = W_C^T

// ============================ helpers ============================
__device__ __forceinline__ void mma_f16(float* d, const uint32_t* a, const uint32_t* b) {
    asm volatile(
        "mma.sync.aligned.m16n8k16.row.col.f32.f16.f16.f32 "
        "{%0,%1,%2,%3}, {%4,%5,%6,%7}, {%8,%9}, {%0,%1,%2,%3};"
        : "+f"(d[0]), "+f"(d[1]), "+f"(d[2]), "+f"(d[3])
        : "r"(a[0]), "r"(a[1]), "r"(a[2]), "r"(a[3]), "r"(b[0]), "r"(b[1]));
}
__device__ __forceinline__ float dt_transform(float v, float Acoef) {
    float sp  = (v > 20.0f) ? v : log1pf(expf(v));
    float dtv = fminf(fmaxf(sp, 1e-4f), 5.0f);
    float la  = fminf(fmaxf(dtv * Acoef, -18.4206807f), 0.0f);
    return expf(la);
}
__device__ __forceinline__ void cpasync16(uint32_t saddr, const void* g) {
    asm volatile("cp.async.cg.shared.global [%0], [%1], 16;" :: "r"(saddr), "l"(g));
}
#define CP_COMMIT() asm volatile("cp.async.commit_group;" ::: "memory")
#define CP_WAIT1()  asm volatile("cp.async.wait_group 1;" ::: "memory")
#define CP_WAIT0()  asm volatile("cp.async.wait_group 0;" ::: "memory")

__device__ __forceinline__ ull pack2(float lo, float hi) {
    ull r; asm("mov.b64 %0, {%1, %2};" : "=l"(r) : "f"(lo), "f"(hi)); return r;
}
__device__ __forceinline__ void unpack2(ull v, float& lo, float& hi) {
    asm("mov.b64 {%0, %1}, %2;" : "=f"(lo), "=f"(hi) : "l"(v));
}
#define FMA2_ACC(d, a, b) \
    asm("fma.rn.f32x2 %0, %1, %2, %0;" : "+l"(d) : "l"(a), "l"(b))
#define MUL2(d, a, b) \
    asm("mul.rn.f32x2 %0, %1, %2;" : "=l"(d) : "l"(a), "l"(b))

// ============================ fp16 GEMM mainloop ============================
// D[128,128] tile = A[row0..+128, 0..512) * Bt[col0..+128, 0..512)^T, fp16 in,
// fp32 accum.  BK=64 (8 chunks), 3 SMEM stages, 1 barrier/chunk.
// 8 warps (2 M x 4 N), warp tile 64x32, m16n8k16.
// SMEM row = 64 fp16 = 32 words, padded to 36 words (same bank pattern as R6).
#define STG_F (128 * 36)    // words per stage
#define NSTG 3

__device__ __forceinline__ void gemm_mainloop(
    const __half* __restrict__ A, const __half* __restrict__ Bt,
    int row0, int col0, float* sm, float acc[4][4][4],
    int tid, int warp_m, int warp_n, int g, int tig)
{
    float* Asm = sm;                 // NSTG stages x 128x36 words
    float* Bsm = sm + NSTG * STG_F;
    const uint32_t asm_u = (uint32_t)__cvta_generic_to_shared(Asm);
    const uint32_t bsm_u = (uint32_t)__cvta_generic_to_shared(Bsm);
    const int ldm = tid >> 3;
    const int ldc16 = tid & 7;       // 16B column within 128B row

    auto issue = [&](int s, int k0) {
        #pragma unroll
        for (int j = 0; j < 4; j++) {
            const int m = ldm + 32 * j;
            const uint32_t off = (uint32_t)((s * STG_F + m * 36 + ldc16 * 4) * 4);
            cpasync16(asm_u + off, &A[(size_t)(row0 + m) * 512 + k0 + ldc16 * 8]);
            cpasync16(bsm_u + off, &Bt[(size_t)(col0 + m) * 512 + k0 + ldc16 * 8]);
        }
        CP_COMMIT();
    };
    issue(0, 0);
    issue(1, 64);

    #pragma unroll 1
    for (int c = 0; c < 8; c++) {
        const int s = c % NSTG;
        if (c < 7) { CP_WAIT1(); } else { CP_WAIT0(); }
        __syncthreads();
        if (c + 2 < 8) issue((c + 2) % NSTG, (c + 2) * 64);
        const uint32_t* AsU = (const uint32_t*)(Asm + s * STG_F);
        const uint32_t* BsU = (const uint32_t*)(Bsm + s * STG_F);
        #pragma unroll
        for (int kk = 0; kk < 4; kk++) {
            const int k = kk * 8;    // 8 words = 16 fp16 per k-step
            uint32_t af[4][4];
            #pragma unroll
            for (int mi = 0; mi < 4; mi++) {
                const int mr = warp_m * 64 + mi * 16 + g;
                af[mi][0] = AsU[mr * 36 + k + tig];
                af[mi][1] = AsU[(mr + 8) * 36 + k + tig];
                af[mi][2] = AsU[mr * 36 + k + tig + 4];
                af[mi][3] = AsU[(mr + 8) * 36 + k + tig + 4];
            }
            #pragma unroll
            for (int ni = 0; ni < 4; ni++) {
                uint32_t bf[2];
                const int nr = warp_n * 32 + ni * 8 + g;
                bf[0] = BsU[nr * 36 + k + tig];
                bf[1] = BsU[nr * 36 + k + tig + 4];
                #pragma unroll
                for (int mi = 0; mi < 4; mi++)
                    mma_f16(acc[mi][ni], af[mi], bf);
            }
        }
    }
    __syncthreads();
}

// ---- EPI 0: +bias -> fout (ldc, fp32).
// ---- EPI 3: xproj: +bias; n<512 -> fp16 x_bar to hout (ld 512);
//             n>=512 -> z fp32 to fout (ld 512, col n-512).
template <int EPI>
__global__ void __launch_bounds__(256, 2)
mma_gemm_k(const __half* __restrict__ A,
           const __half* __restrict__ Bt,
           const float* __restrict__ bias,
           float* __restrict__ fout, __half* __restrict__ hout, int ldc)
{
    extern __shared__ float sm[];
    const int tid = threadIdx.x;
    const int wid = tid >> 5;
    const int lane = tid & 31;
    const int g = lane >> 2;
    const int tig = lane & 3;
    const int warp_m = wid >> 2;
    const int warp_n = wid & 3;
    const int row0 = blockIdx.y * 128;
    const int col0 = blockIdx.x * 128;

    float acc[4][4][4] = {};
    gemm_mainloop(A, Bt, row0, col0, sm, acc, tid, warp_m, warp_n, g, tig);

    #pragma unroll
    for (int mi = 0; mi < 4; mi++) {
        const int m = row0 + warp_m * 64 + mi * 16 + g;
        #pragma unroll
        for (int ni = 0; ni < 4; ni++) {
            const int n = col0 + warp_n * 32 + ni * 8 + 2 * tig;
            float d0 = acc[mi][ni][0], d1 = acc[mi][ni][1];
            float d2 = acc[mi][ni][2], d3 = acc[mi][ni][3];
            const float b0 = bias[n], b1 = bias[n + 1];
            d0 += b0; d1 += b1; d2 += b0; d3 += b1;
            if (EPI == 3) {
                if (n < 512) {
                    *(__half2*)&hout[(size_t)m * 512 + n] = __floats2half2_rn(d0, d1);
                    *(__half2*)&hout[(size_t)(m + 8) * 512 + n] = __floats2half2_rn(d2, d3);
                } else {
                    *(float2*)&fout[(size_t)m * 512 + n - 512] = make_float2(d0, d1);
                    *(float2*)&fout[(size_t)(m + 8) * 512 + n - 512] = make_float2(d2, d3);
                }
            } else {
                *(float2*)&fout[(size_t)m * ldc + n] = make_float2(d0, d1);
                *(float2*)&fout[(size_t)(m + 8) * ldc + n] = make_float2(d2, d3);
            }
        }
    }
}

// ---- merged dt (blockIdx.x<4) + fused B|C rmsnorm (blockIdx.x==4) ----
__global__ void __launch_bounds__(256, 2)
dtbc_gemm_k(const __half* __restrict__ xbt,
            const __half* __restrict__ Wdt, const __half* __restrict__ Wbc,
            const float* __restrict__ dt_bias, const float* __restrict__ Ac,
            float* __restrict__ ax,
            float* __restrict__ Bm, float* __restrict__ Cm,
            const float* __restrict__ gBn, const float* __restrict__ gCn)
{
    extern __shared__ float sm[];
    __shared__ float ssred[256];
    const int tid = threadIdx.x;
    const int wid = tid >> 5;
    const int lane = tid & 31;
    const int g = lane >> 2;
    const int tig = lane & 3;
    const int warp_m = wid >> 2;
    const int warp_n = wid & 3;
    const int row0 = blockIdx.y * 128;
    const bool is_dt = blockIdx.x < 4;
    const int col0 = is_dt ? blockIdx.x * 128 : 0;
    const __half* Bt = is_dt ? Wdt : Wbc;

    if (!is_dt) ssred[tid] = 0.0f;

    float acc[4][4][4] = {};
    gemm_mainloop(xbt, Bt, row0, col0, sm, acc, tid, warp_m, warp_n, g, tig);

    if (is_dt) {
        #pragma unroll
        for (int mi = 0; mi < 4; mi++) {
            const int m = row0 + warp_m * 64 + mi * 16 + g;
            #pragma unroll
            for (int ni = 0; ni < 4; ni++) {
                const int n = col0 + warp_n * 32 + ni * 8 + 2 * tig;
                const float b0 = dt_bias[n], b1 = dt_bias[n + 1];
                const float a0 = Ac[n], a1 = Ac[n + 1];
                *(float2*)&ax[(size_t)m * 512 + n] = make_float2(
                    dt_transform(acc[mi][ni][0] + b0, a0),
                    dt_transform(acc[mi][ni][1] + b1, a1));
                *(float2*)&ax[(size_t)(m + 8) * 512 + n] = make_float2(
                    dt_transform(acc[mi][ni][2] + b0, a0),
                    dt_transform(acc[mi][ni][3] + b1, a1));
            }
        }
    } else {
        const int half = warp_n >> 1;                 // 0 = B, 1 = C
        #pragma unroll
        for (int mi = 0; mi < 4; mi++) {
            float s0 = 0.0f, s1 = 0.0f;
            #pragma unroll
            for (int ni = 0; ni < 4; ni++) {
                s0 += acc[mi][ni][0] * acc[mi][ni][0] + acc[mi][ni][1] * acc[mi][ni][1];
                s1 += acc[mi][ni][2] * acc[mi][ni][2] + acc[mi][ni][3] * acc[mi][ni][3];
            }
            s0 += __shfl_xor_sync(0xffffffffu, s0, 1);
            s0 += __shfl_xor_sync(0xffffffffu, s0, 2);
            s1 += __shfl_xor_sync(0xffffffffu, s1, 1);
            s1 += __shfl_xor_sync(0xffffffffu, s1, 2);
            if (tig == 0) {
                const int r = warp_m * 64 + mi * 16 + g;
                atomicAdd(&ssred[half * 128 + r], s0);
                atomicAdd(&ssred[half * 128 + r + 8], s1);
            }
        }
        __syncthreads();
        const float* gam = half ? gCn : gBn;
        float* outp = half ? Cm : Bm;
        #pragma unroll
        for (int mi = 0; mi < 4; mi++) {
            const int r = warp_m * 64 + mi * 16 + g;
            const float rs0 = rsqrtf(ssred[half * 128 + r] * (1.0f / 64.0f) + 1e-6f);
            const float rs1 = rsqrtf(ssred[half * 128 + r + 8] * (1.0f / 64.0f) + 1e-6f);
            #pragma unroll
            for (int ni = 0; ni < 4; ni++) {
                const int nl = (warp_n - half * 2) * 32 + ni * 8 + 2 * tig;  // 0..63
                const float g0 = gam[nl], g1 = gam[nl + 1];
                *(float2*)&outp[(size_t)(row0 + r) * 64 + nl] =
                    make_float2(acc[mi][ni][0] * rs0 * g0, acc[mi][ni][1] * rs0 * g1);
                *(float2*)&outp[(size_t)(row0 + r + 8) * 64 + nl] =
                    make_float2(acc[mi][ni][2] * rs1 * g0, acc[mi][ni][3] * rs1 * g1);
            }
        }
    }
}

// ============================ prep kernels ============================

__global__ void acoef_k(const float* __restrict__ A_log, float* __restrict__ Ac)
{
    int d = threadIdx.x;
    Ac[d] = -expf(fminf(fmaxf(A_log[d], -20.0f), 2.0f));
}

// [0,4096): round x -> fp16 xt (8 floats/thread). [4096,5184): weight transposes.
__global__ void __launch_bounds__(256)
prep_k(const float* __restrict__ x,
       const float* __restrict__ Wxp, const float* __restrict__ Wdt,
       const float* __restrict__ Wout, const float* __restrict__ WB,
       const float* __restrict__ WC,
       __half* __restrict__ xt, __half* __restrict__ Twxp, __half* __restrict__ Twdt,
       __half* __restrict__ Twout, __half* __restrict__ Twbc)
{
    int bid = blockIdx.x;
    if (bid < 4096) {
        const size_t gi = (size_t)bid * 256 + threadIdx.x;   // 8-float group
        float4 v0 = ((const float4*)x)[gi * 2];
        float4 v1 = ((const float4*)x)[gi * 2 + 1];
        __half2 h0 = __floats2half2_rn(v0.x, v0.y);
        __half2 h1 = __floats2half2_rn(v0.z, v0.w);
        __half2 h2 = __floats2half2_rn(v1.x, v1.y);
        __half2 h3 = __floats2half2_rn(v1.z, v1.w);
        uint4 u;
        u.x = *(uint32_t*)&h0; u.y = *(uint32_t*)&h1;
        u.z = *(uint32_t*)&h2; u.w = *(uint32_t*)&h3;
        ((uint4*)xt)[gi] = u;
        return;
    }
    bid -= 4096;
    const float* W; __half* Wt; int N, lb;
    if (bid < 512)       { W = Wxp;  Wt = Twxp;            N = 1024; lb = bid; }
    else if (bid < 768)  { W = Wdt;  Wt = Twdt;            N = 512;  lb = bid - 512; }
    else if (bid < 1024) { W = Wout; Wt = Twout;           N = 512;  lb = bid - 768; }
    else if (bid < 1056) { W = WB;   Wt = Twbc;            N = 64;   lb = bid - 1024; }
    else                 { W = WC;   Wt = Twbc + 64 * 512; N = 64;   lb = bid - 1056; }
    const int tiles_n = N / 32;
    const int n0 = (lb % tiles_n) * 32;
    const int k0 = (lb / tiles_n) * 32;
    __shared__ float tile[32][33];
    const int tx = threadIdx.x & 31, ty = threadIdx.x >> 5;
    for (int i = ty; i < 32; i += 8)
        tile[i][tx] = W[(size_t)(k0 + i) * N + n0 + tx];
    __syncthreads();
    for (int i = ty; i < 32; i += 8)
        Wt[(size_t)(n0 + i) * 512 + k0 + tx] = __float2half_rn(tile[tx][i]);
}

// ============================ scan kernels ============================

// Intra-chunk recurrence (f32x2, prefetch). Y gets y_intra + D_skip*x_bar.
// x_bar read from fp16 xbt (ld 512).
__global__ void __launch_bounds__(512)
scan_intra_k(const __half* __restrict__ xbt, const float* __restrict__ Bm,
             const float* __restrict__ Cm, const float* __restrict__ Dskip,
             float* __restrict__ ax, float* __restrict__ Y,
             float* __restrict__ cs, float* __restrict__ dtot)
{
    __shared__ float4 Bs[64][16];
    __shared__ float4 Cs[64][16];
    const int blk = blockIdx.x;
    const int d = threadIdx.x;
    const size_t l0 = (size_t)blk * 64;

    for (int t = d; t < 64 * 16; t += 512) {
        int r = t >> 4, c = t & 15;
        Bs[r][c] = ((const float4*)Bm)[(l0 + r) * 16 + c];
        Cs[r][c] = ((const float4*)Cm)[(l0 + r) * 16 + c];
    }
    __syncthreads();

    ull S2[32];
    #pragma unroll
    for (int q = 0; q < 32; q++) S2[q] = 0ull;
    float dec = 1.0f;
    const float dsk = Dskip[d];

    const float* axp = ax + l0 * 512 + d;
    const __half* xpp = xbt + l0 * 512 + d;
    float av = axp[0];
    float xv = __half2float(xpp[0]);

    #pragma unroll 1
    for (int i = 0; i < 64; i++) {
        float av_n = 0.0f, xv_n = 0.0f;
        if (i < 63) {
            av_n = axp[(size_t)(i + 1) * 512];
            xv_n = __half2float(xpp[(size_t)(i + 1) * 512]);
        }
        const size_t m = l0 + i;
        dec *= av;
        ax[m * 512 + d] = dec;
        const ull av2 = pack2(av, av);
        const ull xv2 = pack2(xv, xv);
        const ull* Bp = (const ull*)&Bs[i][0];
        const ull* Cp = (const ull*)&Cs[i][0];
        ull y2 = 0ull;
        #pragma unroll
        for (int q = 0; q < 32; q++) {
            ull bx; MUL2(bx, Bp[q], xv2);
            FMA2_ACC(bx, av2, S2[q]);   // bx = av*S + b*x
            S2[q] = bx;
            FMA2_ACC(y2, Cp[q], S2[q]);
        }
        float ylo, yhi; unpack2(y2, ylo, yhi);
        Y[m * 512 + d] = ylo + yhi + dsk * xv;
        av = av_n; xv = xv_n;
    }

    #pragma unroll
    for (int q = 0; q < 32; q++) {
        float slo, shi; unpack2(S2[q], slo, shi);
        cs[((size_t)blk * 64 + 2 * q) * 512 + d] = slo;
        cs[((size_t)blk * 64 + 2 * q + 1) * 512 + d] = shi;
    }
    dtot[(size_t)blk * 512 + d] = dec;
}

// Inter-chunk state scan (prefetch), float4 over d; cs -> prev_state in place.
__global__ void state_scan_k(float* __restrict__ cs, const float* __restrict__ dtot)
{
    const int idx = blockIdx.x * blockDim.x + threadIdx.x;   // B*N*128 = 32768
    const int d4 = idx & 127;
    const int n = (idx >> 7) & 63;
    const int b = idx >> 13;
    float4* cs4 = (float4*)cs;
    const float4* dt4 = (const float4*)dtot;
    float4 s = make_float4(0.f, 0.f, 0.f, 0.f);

    size_t off = ((size_t)(b * 64) * 64 + n) * 128 + d4;
    float4 v = cs4[off];
    float4 a = dt4[(size_t)(b * 64) * 128 + d4];

    #pragma unroll 1
    for (int ch = 0; ch < 64; ch++) {
        float4 vn, an;
        if (ch < 63) {
            const int blkn = b * 64 + ch + 1;
            vn = cs4[((size_t)blkn * 64 + n) * 128 + d4];
            an = dt4[(size_t)blkn * 128 + d4];
        } else { vn = s; an = s; }
        cs4[off] = s;
        s.x = fmaf(s.x, a.x, v.x);
        s.y = fmaf(s.y, a.y, v.y);
        s.z = fmaf(s.z, a.z, v.z);
        s.w = fmaf(s.w, a.w, v.w);
        off = ((size_t)(b * 64 + ch + 1) * 64 + n) * 128 + d4;
        v = vn; a = an;
    }
}

// y += decay * (C @ prev_state)   (f32x2; D_skip already folded in scan_intra)
__global__ void __launch_bounds__(512)
yinter_k(const float* __restrict__ Cm, const float* __restrict__ ps,
         const float* __restrict__ decay, float* __restrict__ Y)
{
    __shared__ float4 Cs[64][16];
    const int blk = blockIdx.x;
    const int d = threadIdx.x;
    const size_t l0 = (size_t)blk * 64;

    for (int t = d; t < 64 * 16; t += 512) {
        int r = t >> 4, c = t & 15;
        Cs[r][c] = ((const float4*)Cm)[(l0 + r) * 16 + c];
    }
    __syncthreads();

    ull PS2[32];
    #pragma unroll
    for (int q = 0; q < 32; q++)
        PS2[q] = pack2(ps[((size_t)blk * 64 + 2 * q) * 512 + d],
                       ps[((size_t)blk * 64 + 2 * q + 1) * 512 + d]);

    float dc = decay[l0 * 512 + d];
    float yv = Y[l0 * 512 + d];

    #pragma unroll 1
    for (int i = 0; i < 64; i++) {
        float dc_n = 0.0f, yv_n = 0.0f;
        if (i < 63) {
            dc_n = decay[(l0 + i + 1) * 512 + d];
            yv_n = Y[(l0 + i + 1) * 512 + d];
        }
        const ull* Cp = (const ull*)&Cs[i][0];
        ull y2 = 0ull;
        #pragma unroll
        for (int q = 0; q < 32; q++)
            FMA2_ACC(y2, Cp[q], PS2[q]);
        float ylo, yhi; unpack2(y2, ylo, yhi);
        Y[(l0 + i) * 512 + d] = yv + dc * (ylo + yhi);
        dc = dc_n; yv = yv_n;
    }
}

// h = fp16(rmsnorm(y, g) * silu(z)) -> hbuf; z from zbuf (ld 512).
__global__ void outnorm_k(const float* __restrict__ Y, const float* __restrict__ zb,
                          const float* __restrict__ g, __half* __restrict__ hb)
{
    __shared__ float red[256];
    const int m = blockIdx.x;
    const int t = threadIdx.x;
    float v0 = Y[(size_t)m * 512 + t];
    float v1 = Y[(size_t)m * 512 + t + 256];
    red[t] = v0 * v0 + v1 * v1;
    __syncthreads();
    for (int s = 128; s > 0; s >>= 1) {
        if (t < s) red[t] += red[t + s];
        __syncthreads();
    }
    float rs = rsqrtf(red[0] * (1.0f / 512.0f) + 1e-6f);
    float z0 = zb[(size_t)m * 512 + t];
    float z1 = zb[(size_t)m * 512 + t + 256];
    float s0 = z0 / (1.0f + expf(-z0));
    float s1 = z1 / (1.0f + expf(-z1));
    hb[(size_t)m * 512 + t]       = __float2half_rn(v0 * rs * g[t] * s0);
    hb[(size_t)m * 512 + t + 256] = __float2half_rn(v1 * rs * g[t + 256] * s1);
}

// ============================ launch ============================
#define GEMM_SMEM (NSTG * STG_F * 4 * 2)   // 110592 bytes

extern "C" void kernel_launch(void* const* d_in, const int* in_sizes, int n_in,
                              void* d_out, int out_size)
{
    const float* x       = (const float*)d_in[0];
    const float* A_log   = (const float*)d_in[1];
    const float* dt_bias = (const float*)d_in[2];
    const float* D_skip  = (const float*)d_in[3];
    const float* W_xproj = (const float*)d_in[4];
    const float* b_xproj = (const float*)d_in[5];
    const float* W_B     = (const float*)d_in[6];
    const float* W_C     = (const float*)d_in[7];
    const float* W_dt    = (const float*)d_in[8];
    const float* g_Bn    = (const float*)d_in[9];
    const float* g_Cn    = (const float*)d_in[10];
    const float* g_on    = (const float*)d_in[11];
    const float* W_out   = (const float*)d_in[12];
    const float* b_out   = (const float*)d_in[13];
    float* out = (float*)d_out;

    float *p_z, *p_Bm, *p_Cm, *p_ax, *p_Y, *p_cs, *p_dt, *p_Ac;
    __half *p_xt, *p_xbt, *p_h, *p_Wxp, *p_Wdt, *p_Wout, *p_Wbc;
    cudaGetSymbolAddress((void**)&p_z,   g_z);
    cudaGetSymbolAddress((void**)&p_xt,  g_xt);
    cudaGetSymbolAddress((void**)&p_xbt, g_xbt);
    cudaGetSymbolAddress((void**)&p_h,   g_h);
    cudaGetSymbolAddress((void**)&p_Bm,  g_Bm);
    cudaGetSymbolAddress((void**)&p_Cm,  g_Cm);
    cudaGetSymbolAddress((void**)&p_ax,  g_ax);
    cudaGetSymbolAddress((void**)&p_Y,   g_Yb);
    cudaGetSymbolAddress((void**)&p_cs,  g_cs);
    cudaGetSymbolAddress((void**)&p_dt,  g_dtot);
    cudaGetSymbolAddress((void**)&p_Ac,  g_Ac);
    cudaGetSymbolAddress((void**)&p_Wxp,  g_Wt_xp);
    cudaGetSymbolAddress((void**)&p_Wdt,  g_Wt_dt);
    cudaGetSymbolAddress((void**)&p_Wout, g_Wt_out);
    cudaGetSymbolAddress((void**)&p_Wbc,  g_Wt_bc);

    cudaFuncSetAttribute(mma_gemm_k<0>, cudaFuncAttributeMaxDynamicSharedMemorySize, GEMM_SMEM);
    cudaFuncSetAttribute(mma_gemm_k<3>, cudaFuncAttributeMaxDynamicSharedMemorySize, GEMM_SMEM);
    cudaFuncSetAttribute(dtbc_gemm_k,   cudaFuncAttributeMaxDynamicSharedMemorySize, GEMM_SMEM);

    // 0: A coefficient
    acoef_k<<<1, 512>>>(A_log, p_Ac);
    // 1: weight transposes + x -> fp16
    prep_k<<<5184, 256>>>(x, W_xproj, W_dt, W_out, W_B, W_C,
                          p_xt, p_Wxp, p_Wdt, p_Wout, p_Wbc);
    // 2: xproj: z -> p_z (fp32), fp16 x_bar -> p_xbt
    mma_gemm_k<3><<<dim3(8, 128), 256, GEMM_SMEM>>>(
        p_xt, p_Wxp, b_xproj, p_z, p_xbt, 512);
    // 3: merged dt-GEMM + fused B|C projection + rmsnorm (one wave)
    dtbc_gemm_k<<<dim3(5, 128), 256, GEMM_SMEM>>>(
        p_xbt, p_Wdt, p_Wbc, dt_bias, p_Ac, p_ax, p_Bm, p_Cm, g_Bn, g_Cn);
    // 4: intra-chunk recurrence (+ D_skip*x_bar folded)
    scan_intra_k<<<NBLK, 512>>>(p_xbt, p_Bm, p_Cm, D_skip, p_ax, p_Y, p_cs, p_dt);
    // 5: inter-chunk state scan
    state_scan_k<<<(BQ * NQ * 128) / 256, 256>>>(p_cs, p_dt);
    // 6: y += decay * (C @ prev_state)
    yinter_k<<<NBLK, 512>>>(p_Cm, p_cs, p_ax, p_Y);
    // 7: h = rmsnorm(y) * silu(z) -> fp16
    outnorm_k<<<MQ, 256>>>(p_Y, p_z, g_on, p_h);
    // 8: out = h @ W_out + b_out
    mma_gemm_k<0><<<dim3(4, 128), 256, GEMM_SMEM>>>(
        p_h, p_Wout, b_out, out, nullptr, 512);
}

// round 12
// speedup vs baseline: 1.4415x; 1.0469x over previous
#include <cuda_runtime.h>
#include <cuda_fp16.h>
#include <math.h>
#include <stdint.h>

// Problem constants (fixed shapes)
#define BQ 4
#define LQ 4096
#define DQ 512
#define NQ 64
#define MQ (BQ * LQ)        // 16384 rows
#define NBLK 256            // (b,chunk) blocks, chunk=64

typedef unsigned long long ull;

// -------- scratch (device globals; no allocation allowed) --------
__device__ float  g_z[(size_t)MQ * 512];          // z half of xproj (ld 512)
__device__ __half g_xt[(size_t)MQ * 512];         // fp16 x
__device__ __half g_xbt[(size_t)MQ * 512];        // fp16 x_bar
__device__ __half g_h[(size_t)MQ * 512];          // fp16 h (outnorm output)
__device__ float  g_Bm[(size_t)MQ * 64];          // B proj (rmsnormed)
__device__ float  g_Cm[(size_t)MQ * 64];          // C proj (rmsnormed)
__device__ float  g_ax[(size_t)MQ * 512];         // a=exp(la) -> cumulative decay
__device__ float  g_Yb[(size_t)MQ * 512];         // y buffer (fp32)
__device__ float  g_cs[(size_t)NBLK * 64 * 512];  // chunk states -> prev states
__device__ float  g_dtot[(size_t)NBLK * 512];     // per-chunk total decay
__device__ float  g_Ac[512];                      // A coefficient
// transposed fp16 weights: Wt[n][k], k contiguous (512)
__device__ __half g_Wt_xp[1024 * 512];
__device__ __half g_Wt_dt[512 * 512];
__device__ __half g_Wt_out[512 * 512];
__device__ __half g_Wt_bc[128 * 512];             // rows 0..63 = W_B^T, 64..127 = W_C^T

// ============================ helpers ============================
__device__ __forceinline__ void mma_f16(float* d, const uint32_t* a,
                                        uint32_t b0, uint32_t b1) {
    asm volatile(
        "mma.sync.aligned.m16n8k16.row.col.f32.f16.f16.f32 "
        "{%0,%1,%2,%3}, {%4,%5,%6,%7}, {%8,%9}, {%0,%1,%2,%3};"
        : "+f"(d[0]), "+f"(d[1]), "+f"(d[2]), "+f"(d[3])
        : "r"(a[0]), "r"(a[1]), "r"(a[2]), "r"(a[3]), "r"(b0), "r"(b1));
}
__device__ __forceinline__ void ldsm4(uint32_t* r, uint32_t addr) {
    asm volatile("ldmatrix.sync.aligned.m8n8.x4.shared.b16 {%0,%1,%2,%3}, [%4];"
                 : "=r"(r[0]), "=r"(r[1]), "=r"(r[2]), "=r"(r[3]) : "r"(addr));
}
__device__ __forceinline__ float dt_transform(float v, float Acoef) {
    float sp  = (v > 20.0f) ? v : log1pf(expf(v));
    float dtv = fminf(fmaxf(sp, 1e-4f), 5.0f);
    float la  = fminf(fmaxf(dtv * Acoef, -18.4206807f), 0.0f);
    return expf(la);
}
__device__ __forceinline__ void cpasync16(uint32_t saddr, const void* g) {
    asm volatile("cp.async.cg.shared.global [%0], [%1], 16;" :: "r"(saddr), "l"(g));
}
#define CP_COMMIT() asm volatile("cp.async.commit_group;" ::: "memory")
#define CP_WAIT1()  asm volatile("cp.async.wait_group 1;" ::: "memory")
#define CP_WAIT0()  asm volatile("cp.async.wait_group 0;" ::: "memory")

__device__ __forceinline__ ull pack2(float lo, float hi) {
    ull r; asm("mov.b64 %0, {%1, %2};" : "=l"(r) : "f"(lo), "f"(hi)); return r;
}
__device__ __forceinline__ void unpack2(ull v, float& lo, float& hi) {
    asm("mov.b64 {%0, %1}, %2;" : "=f"(lo), "=f"(hi) : "l"(v));
}
#define FMA2_ACC(d, a, b) \
    asm("fma.rn.f32x2 %0, %1, %2, %0;" : "+l"(d) : "l"(a), "l"(b))
#define MUL2(d, a, b) \
    asm("mul.rn.f32x2 %0, %1, %2;" : "=l"(d) : "l"(a), "l"(b))

// ============================ fp16 GEMM mainloop (ldmatrix) ============================
// D[128,128] tile = A[row0..+128, 0..512) * Bt[col0..+128, 0..512)^T, fp16 in,
// fp32 accum.  BK=64 (8 chunks), 3 SMEM stages, 1 barrier/chunk.
// 8 warps (2 M x 4 N), warp tile 64x32, m16n8k16; fragments via ldmatrix.x4.
#define STG_F (128 * 36)    // words per stage
#define NSTG 3

__device__ __forceinline__ void gemm_mainloop(
    const __half* __restrict__ A, const __half* __restrict__ Bt,
    int row0, int col0, float* sm, float acc[4][4][4],
    int tid, int warp_m, int warp_n, int lane)
{
    float* Asm = sm;                 // NSTG stages x 128x36 words
    float* Bsm = sm + NSTG * STG_F;
    const uint32_t asm_u = (uint32_t)__cvta_generic_to_shared(Asm);
    const uint32_t bsm_u = (uint32_t)__cvta_generic_to_shared(Bsm);
    const int ldm = tid >> 3;
    const int ldc16 = tid & 7;       // 16B column within 128B row

    auto issue = [&](int s, int k0) {
        #pragma unroll
        for (int j = 0; j < 4; j++) {
            const int m = ldm + 32 * j;
            const uint32_t off = (uint32_t)((s * STG_F + m * 36 + ldc16 * 4) * 4);
            cpasync16(asm_u + off, &A[(size_t)(row0 + m) * 512 + k0 + ldc16 * 8]);
            cpasync16(bsm_u + off, &Bt[(size_t)(col0 + m) * 512 + k0 + ldc16 * 8]);
        }
        CP_COMMIT();
    };
    issue(0, 0);
    issue(1, 64);

    // ldmatrix lane geometry (byte offsets within a stage)
    const int a_row = warp_m * 64 + ((lane >> 3) & 1) * 8 + (lane & 7);
    const int a_col = (lane >> 4) * 4;                     // words
    uint32_t a_base[4];
    #pragma unroll
    for (int mi = 0; mi < 4; mi++)
        a_base[mi] = (uint32_t)(((a_row + mi * 16) * 36 + a_col) * 4);
    const int b_row = warp_n * 32 + (lane >> 4) * 8 + (lane & 7);
    const int b_col = ((lane >> 3) & 1) * 4;               // words
    uint32_t b_base[2];
    #pragma unroll
    for (int nj = 0; nj < 2; nj++)
        b_base[nj] = (uint32_t)(((b_row + nj * 16) * 36 + b_col) * 4);

    #pragma unroll 1
    for (int c = 0; c < 8; c++) {
        const int s = c % NSTG;
        if (c < 7) { CP_WAIT1(); } else { CP_WAIT0(); }
        __syncthreads();
        if (c + 2 < 8) issue((c + 2) % NSTG, (c + 2) * 64);
        const uint32_t abase_s = asm_u + (uint32_t)(s * STG_F * 4);
        const uint32_t bbase_s = bsm_u + (uint32_t)(s * STG_F * 4);
        #pragma unroll
        for (int kk = 0; kk < 4; kk++) {
            const uint32_t koff = kk * 32;   // 8 words = 32 bytes per k-step
            uint32_t af[4][4];
            #pragma unroll
            for (int mi = 0; mi < 4; mi++)
                ldsm4(af[mi], abase_s + a_base[mi] + koff);
            uint32_t bf[2][4];
            #pragma unroll
            for (int nj = 0; nj < 2; nj++)
                ldsm4(bf[nj], bbase_s + b_base[nj] + koff);
            #pragma unroll
            for (int ni = 0; ni < 4; ni++) {
                const uint32_t b0 = bf[ni >> 1][(ni & 1) * 2];
                const uint32_t b1 = bf[ni >> 1][(ni & 1) * 2 + 1];
                #pragma unroll
                for (int mi = 0; mi < 4; mi++)
                    mma_f16(acc[mi][ni], af[mi], b0, b1);
            }
        }
    }
    __syncthreads();
}

// ---- EPI 0: +bias -> fout (ldc, fp32).
// ---- EPI 3: xproj: +bias; n<512 -> fp16 x_bar to hout (ld 512);
//             n>=512 -> z fp32 to fout (ld 512, col n-512).
template <int EPI>
__global__ void __launch_bounds__(256, 2)
mma_gemm_k(const __half* __restrict__ A,
           const __half* __restrict__ Bt,
           const float* __restrict__ bias,
           float* __restrict__ fout, __half* __restrict__ hout, int ldc)
{
    extern __shared__ float sm[];
    const int tid = threadIdx.x;
    const int wid = tid >> 5;
    const int lane = tid & 31;
    const int g = lane >> 2;
    const int tig = lane & 3;
    const int warp_m = wid >> 2;
    const int warp_n = wid & 3;
    const int row0 = blockIdx.y * 128;
    const int col0 = blockIdx.x * 128;

    float acc[4][4][4] = {};
    gemm_mainloop(A, Bt, row0, col0, sm, acc, tid, warp_m, warp_n, lane);

    #pragma unroll
    for (int mi = 0; mi < 4; mi++) {
        const int m = row0 + warp_m * 64 + mi * 16 + g;
        #pragma unroll
        for (int ni = 0; ni < 4; ni++) {
            const int n = col0 + warp_n * 32 + ni * 8 + 2 * tig;
            float d0 = acc[mi][ni][0], d1 = acc[mi][ni][1];
            float d2 = acc[mi][ni][2], d3 = acc[mi][ni][3];
            const float b0 = bias[n], b1 = bias[n + 1];
            d0 += b0; d1 += b1; d2 += b0; d3 += b1;
            if (EPI == 3) {
                if (n < 512) {
                    *(__half2*)&hout[(size_t)m * 512 + n] = __floats2half2_rn(d0, d1);
                    *(__half2*)&hout[(size_t)(m + 8) * 512 + n] = __floats2half2_rn(d2, d3);
                } else {
                    *(float2*)&fout[(size_t)m * 512 + n - 512] = make_float2(d0, d1);
                    *(float2*)&fout[(size_t)(m + 8) * 512 + n - 512] = make_float2(d2, d3);
                }
            } else {
                *(float2*)&fout[(size_t)m * ldc + n] = make_float2(d0, d1);
                *(float2*)&fout[(size_t)(m + 8) * ldc + n] = make_float2(d2, d3);
            }
        }
    }
}

// ---- merged dt (blockIdx.x<4) + fused B|C rmsnorm (blockIdx.x==4) ----
__global__ void __launch_bounds__(256, 2)
dtbc_gemm_k(const __half* __restrict__ xbt,
            const __half* __restrict__ Wdt, const __half* __restrict__ Wbc,
            const float* __restrict__ dt_bias, const float* __restrict__ Ac,
            float* __restrict__ ax,
            float* __restrict__ Bm, float* __restrict__ Cm,
            const float* __restrict__ gBn, const float* __restrict__ gCn)
{
    extern __shared__ float sm[];
    __shared__ float ssred[256];
    const int tid = threadIdx.x;
    const int wid = tid >> 5;
    const int lane = tid & 31;
    const int g = lane >> 2;
    const int tig = lane & 3;
    const int warp_m = wid >> 2;
    const int warp_n = wid & 3;
    const int row0 = blockIdx.y * 128;
    const bool is_dt = blockIdx.x < 4;
    const int col0 = is_dt ? blockIdx.x * 128 : 0;
    const __half* Bt = is_dt ? Wdt : Wbc;

    if (!is_dt) ssred[tid] = 0.0f;

    float acc[4][4][4] = {};
    gemm_mainloop(xbt, Bt, row0, col0, sm, acc, tid, warp_m, warp_n, lane);

    if (is_dt) {
        #pragma unroll
        for (int mi = 0; mi < 4; mi++) {
            const int m = row0 + warp_m * 64 + mi * 16 + g;
            #pragma unroll
            for (int ni = 0; ni < 4; ni++) {
                const int n = col0 + warp_n * 32 + ni * 8 + 2 * tig;
                const float b0 = dt_bias[n], b1 = dt_bias[n + 1];
                const float a0 = Ac[n], a1 = Ac[n + 1];
                *(float2*)&ax[(size_t)m * 512 + n] = make_float2(
                    dt_transform(acc[mi][ni][0] + b0, a0),
                    dt_transform(acc[mi][ni][1] + b1, a1));
                *(float2*)&ax[(size_t)(m + 8) * 512 + n] = make_float2(
                    dt_transform(acc[mi][ni][2] + b0, a0),
                    dt_transform(acc[mi][ni][3] + b1, a1));
            }
        }
    } else {
        const int half = warp_n >> 1;                 // 0 = B, 1 = C
        #pragma unroll
        for (int mi = 0; mi < 4; mi++) {
            float s0 = 0.0f, s1 = 0.0f;
            #pragma unroll
            for (int ni = 0; ni < 4; ni++) {
                s0 += acc[mi][ni][0] * acc[mi][ni][0] + acc[mi][ni][1] * acc[mi][ni][1];
                s1 += acc[mi][ni][2] * acc[mi][ni][2] + acc[mi][ni][3] * acc[mi][ni][3];
            }
            s0 += __shfl_xor_sync(0xffffffffu, s0, 1);
            s0 += __shfl_xor_sync(0xffffffffu, s0, 2);
            s1 += __shfl_xor_sync(0xffffffffu, s1, 1);
            s1 += __shfl_xor_sync(0xffffffffu, s1, 2);
            if (tig == 0) {
                const int r = warp_m * 64 + mi * 16 + g;
                atomicAdd(&ssred[half * 128 + r], s0);
                atomicAdd(&ssred[half * 128 + r + 8], s1);
            }
        }
        __syncthreads();
        const float* gam = half ? gCn : gBn;
        float* outp = half ? Cm : Bm;
        #pragma unroll
        for (int mi = 0; mi < 4; mi++) {
            const int r = warp_m * 64 + mi * 16 + g;
            const float rs0 = rsqrtf(ssred[half * 128 + r] * (1.0f / 64.0f) + 1e-6f);
            const float rs1 = rsqrtf(ssred[half * 128 + r + 8] * (1.0f / 64.0f) + 1e-6f);
            #pragma unroll
            for (int ni = 0; ni < 4; ni++) {
                const int nl = (warp_n - half * 2) * 32 + ni * 8 + 2 * tig;  // 0..63
                const float g0 = gam[nl], g1 = gam[nl + 1];
                *(float2*)&outp[(size_t)(row0 + r) * 64 + nl] =
                    make_float2(acc[mi][ni][0] * rs0 * g0, acc[mi][ni][1] * rs0 * g1);
                *(float2*)&outp[(size_t)(row0 + r + 8) * 64 + nl] =
                    make_float2(acc[mi][ni][2] * rs1 * g0, acc[mi][ni][3] * rs1 * g1);
            }
        }
    }
}

// ============================ prep kernels ============================

__global__ void acoef_k(const float* __restrict__ A_log, float* __restrict__ Ac)
{
    int d = threadIdx.x;
    Ac[d] = -expf(fminf(fmaxf(A_log[d], -20.0f), 2.0f));
}

// [0,4096): round x -> fp16 xt (8 floats/thread). [4096,5184): weight transposes.
__global__ void __launch_bounds__(256)
prep_k(const float* __restrict__ x,
       const float* __restrict__ Wxp, const float* __restrict__ Wdt,
       const float* __restrict__ Wout, const float* __restrict__ WB,
       const float* __restrict__ WC,
       __half* __restrict__ xt, __half* __restrict__ Twxp, __half* __restrict__ Twdt,
       __half* __restrict__ Twout, __half* __restrict__ Twbc)
{
    int bid = blockIdx.x;
    if (bid < 4096) {
        const size_t gi = (size_t)bid * 256 + threadIdx.x;   // 8-float group
        float4 v0 = ((const float4*)x)[gi * 2];
        float4 v1 = ((const float4*)x)[gi * 2 + 1];
        __half2 h0 = __floats2half2_rn(v0.x, v0.y);
        __half2 h1 = __floats2half2_rn(v0.z, v0.w);
        __half2 h2 = __floats2half2_rn(v1.x, v1.y);
        __half2 h3 = __floats2half2_rn(v1.z, v1.w);
        uint4 u;
        u.x = *(uint32_t*)&h0; u.y = *(uint32_t*)&h1;
        u.z = *(uint32_t*)&h2; u.w = *(uint32_t*)&h3;
        ((uint4*)xt)[gi] = u;
        return;
    }
    bid -= 4096;
    const float* W; __half* Wt; int N, lb;
    if (bid < 512)       { W = Wxp;  Wt = Twxp;            N = 1024; lb = bid; }
    else if (bid < 768)  { W = Wdt;  Wt = Twdt;            N = 512;  lb = bid - 512; }
    else if (bid < 1024) { W = Wout; Wt = Twout;           N = 512;  lb = bid - 768; }
    else if (bid < 1056) { W = WB;   Wt = Twbc;            N = 64;   lb = bid - 1024; }
    else                 { W = WC;   Wt = Twbc + 64 * 512; N = 64;   lb = bid - 1056; }
    const int tiles_n = N / 32;
    const int n0 = (lb % tiles_n) * 32;
    const int k0 = (lb / tiles_n) * 32;
    __shared__ float tile[32][33];
    const int tx = threadIdx.x & 31, ty = threadIdx.x >> 5;
    for (int i = ty; i < 32; i += 8)
        tile[i][tx] = W[(size_t)(k0 + i) * N + n0 + tx];
    __syncthreads();
    for (int i = ty; i < 32; i += 8)
        Wt[(size_t)(n0 + i) * 512 + k0 + tx] = __float2half_rn(tile[tx][i]);
}

// ============================ scan kernels ============================

// Intra-chunk recurrence (f32x2, LDS.128 tile reads, prefetch).
// Y gets y_intra + D_skip*x_bar; x_bar from fp16 xbt (ld 512).
__global__ void __launch_bounds__(512)
scan_intra_k(const __half* __restrict__ xbt, const float* __restrict__ Bm,
             const float* __restrict__ Cm, const float* __restrict__ Dskip,
             float* __restrict__ ax, float* __restrict__ Y,
             float* __restrict__ cs, float* __restrict__ dtot)
{
    __shared__ float4 Bs[64][16];
    __shared__ float4 Cs[64][16];
    const int blk = blockIdx.x;
    const int d = threadIdx.x;
    const size_t l0 = (size_t)blk * 64;

    for (int t = d; t < 64 * 16; t += 512) {
        int r = t >> 4, c = t & 15;
        Bs[r][c] = ((const float4*)Bm)[(l0 + r) * 16 + c];
        Cs[r][c] = ((const float4*)Cm)[(l0 + r) * 16 + c];
    }
    __syncthreads();

    ull S2[32];
    #pragma unroll
    for (int q = 0; q < 32; q++) S2[q] = 0ull;
    float dec = 1.0f;
    const float dsk = Dskip[d];

    const float* axp = ax + l0 * 512 + d;
    const __half* xpp = xbt + l0 * 512 + d;
    float av = axp[0];
    float xv = __half2float(xpp[0]);

    #pragma unroll 1
    for (int i = 0; i < 64; i++) {
        float av_n = 0.0f, xv_n = 0.0f;
        if (i < 63) {
            av_n = axp[(size_t)(i + 1) * 512];
            xv_n = __half2float(xpp[(size_t)(i + 1) * 512]);
        }
        const size_t m = l0 + i;
        dec *= av;
        ax[m * 512 + d] = dec;
        const ull av2 = pack2(av, av);
        const ull xv2 = pack2(xv, xv);
        const ulonglong2* Bp2 = (const ulonglong2*)&Bs[i][0];
        const ulonglong2* Cp2 = (const ulonglong2*)&Cs[i][0];
        ull y2 = 0ull;
        #pragma unroll
        for (int q2 = 0; q2 < 16; q2++) {
            const ulonglong2 b2 = Bp2[q2];
            const ulonglong2 c2 = Cp2[q2];
            ull bx0; MUL2(bx0, b2.x, xv2);
            FMA2_ACC(bx0, av2, S2[2 * q2]);
            S2[2 * q2] = bx0;
            FMA2_ACC(y2, c2.x, S2[2 * q2]);
            ull bx1; MUL2(bx1, b2.y, xv2);
            FMA2_ACC(bx1, av2, S2[2 * q2 + 1]);
            S2[2 * q2 + 1] = bx1;
            FMA2_ACC(y2, c2.y, S2[2 * q2 + 1]);
        }
        float ylo, yhi; unpack2(y2, ylo, yhi);
        Y[m * 512 + d] = ylo + yhi + dsk * xv;
        av = av_n; xv = xv_n;
    }

    #pragma unroll
    for (int q = 0; q < 32; q++) {
        float slo, shi; unpack2(S2[q], slo, shi);
        cs[((size_t)blk * 64 + 2 * q) * 512 + d] = slo;
        cs[((size_t)blk * 64 + 2 * q + 1) * 512 + d] = shi;
    }
    dtot[(size_t)blk * 512 + d] = dec;
}

// Inter-chunk state scan (prefetch), float4 over d; cs -> prev_state in place.
__global__ void state_scan_k(float* __restrict__ cs, const float* __restrict__ dtot)
{
    const int idx = blockIdx.x * blockDim.x + threadIdx.x;   // B*N*128 = 32768
    const int d4 = idx & 127;
    const int n = (idx >> 7) & 63;
    const int b = idx >> 13;
    float4* cs4 = (float4*)cs;
    const float4* dt4 = (const float4*)dtot;
    float4 s = make_float4(0.f, 0.f, 0.f, 0.f);

    size_t off = ((size_t)(b * 64) * 64 + n) * 128 + d4;
    float4 v = cs4[off];
    float4 a = dt4[(size_t)(b * 64) * 128 + d4];

    #pragma unroll 1
    for (int ch = 0; ch < 64; ch++) {
        float4 vn, an;
        if (ch < 63) {
            const int blkn = b * 64 + ch + 1;
            vn = cs4[((size_t)blkn * 64 + n) * 128 + d4];
            an = dt4[(size_t)blkn * 128 + d4];
        } else { vn = s; an = s; }
        cs4[off] = s;
        s.x = fmaf(s.x, a.x, v.x);
        s.y = fmaf(s.y, a.y, v.y);
        s.z = fmaf(s.z, a.z, v.z);
        s.w = fmaf(s.w, a.w, v.w);
        off = ((size_t)(b * 64 + ch + 1) * 64 + n) * 128 + d4;
        v = vn; a = an;
    }
}

// y += decay * (C @ prev_state)   (f32x2, LDS.128 tile reads)
__global__ void __launch_bounds__(512)
yinter_k(const float* __restrict__ Cm, const float* __restrict__ ps,
         const float* __restrict__ decay, float* __restrict__ Y)
{
    __shared__ float4 Cs[64][16];
    const int blk = blockIdx.x;
    const int d = threadIdx.x;
    const size_t l0 = (size_t)blk * 64;

    for (int t = d; t < 64 * 16; t += 512) {
        int r = t >> 4, c = t & 15;
        Cs[r][c] = ((const float4*)Cm)[(l0 + r) * 16 + c];
    }
    __syncthreads();

    ull PS2[32];
    #pragma unroll
    for (int q = 0; q < 32; q++)
        PS2[q] = pack2(ps[((size_t)blk * 64 + 2 * q) * 512 + d],
                       ps[((size_t)blk * 64 + 2 * q + 1) * 512 + d]);

    float dc = decay[l0 * 512 + d];
    float yv = Y[l0 * 512 + d];

    #pragma unroll 1
    for (int i = 0; i < 64; i++) {
        float dc_n = 0.0f, yv_n = 0.0f;
        if (i < 63) {
            dc_n = decay[(l0 + i + 1) * 512 + d];
            yv_n = Y[(l0 + i + 1) * 512 + d];
        }
        const ulonglong2* Cp2 = (const ulonglong2*)&Cs[i][0];
        ull y2 = 0ull;
        #pragma unroll
        for (int q2 = 0; q2 < 16; q2++) {
            const ulonglong2 c2 = Cp2[q2];
            FMA2_ACC(y2, c2.x, PS2[2 * q2]);
            FMA2_ACC(y2, c2.y, PS2[2 * q2 + 1]);
        }
        float ylo, yhi; unpack2(y2, ylo, yhi);
        Y[(l0 + i) * 512 + d] = yv + dc * (ylo + yhi);
        dc = dc_n; yv = yv_n;
    }
}

// h = fp16(rmsnorm(y, g) * silu(z)) -> hbuf; z from zbuf (ld 512).
__global__ void outnorm_k(const float* __restrict__ Y, const float* __restrict__ zb,
                          const float* __restrict__ g, __half* __restrict__ hb)
{
    __shared__ float red[256];
    const int m = blockIdx.x;
    const int t = threadIdx.x;
    float v0 = Y[(size_t)m * 512 + t];
    float v1 = Y[(size_t)m * 512 + t + 256];
    red[t] = v0 * v0 + v1 * v1;
    __syncthreads();
    for (int s = 128; s > 0; s >>= 1) {
        if (t < s) red[t] += red[t + s];
        __syncthreads();
    }
    float rs = rsqrtf(red[0] * (1.0f / 512.0f) + 1e-6f);
    float z0 = zb[(size_t)m * 512 + t];
    float z1 = zb[(size_t)m * 512 + t + 256];
    float s0 = z0 / (1.0f + expf(-z0));
    float s1 = z1 / (1.0f + expf(-z1));
    hb[(size_t)m * 512 + t]       = __float2half_rn(v0 * rs * g[t] * s0);
    hb[(size_t)m * 512 + t + 256] = __float2half_rn(v1 * rs * g[t + 256] * s1);
}

// ============================ launch ============================
#define GEMM_SMEM (NSTG * STG_F * 4 * 2)   // 110592 bytes

extern "C" void kernel_launch(void* const* d_in, const int* in_sizes, int n_in,
                              void* d_out, int out_size)
{
    const float* x       = (const float*)d_in[0];
    const float* A_log   = (const float*)d_in[1];
    const float* dt_bias = (const float*)d_in[2];
    const float* D_skip  = (const float*)d_in[3];
    const float* W_xproj = (const float*)d_in[4];
    const float* b_xproj = (const float*)d_in[5];
    const float* W_B     = (const float*)d_in[6];
    const float* W_C     = (const float*)d_in[7];
    const float* W_dt    = (const float*)d_in[8];
    const float* g_Bn    = (const float*)d_in[9];
    const float* g_Cn    = (const float*)d_in[10];
    const float* g_on    = (const float*)d_in[11];
    const float* W_out   = (const float*)d_in[12];
    const float* b_out   = (const float*)d_in[13];
    float* out = (float*)d_out;

    float *p_z, *p_Bm, *p_Cm, *p_ax, *p_Y, *p_cs, *p_dt, *p_Ac;
    __half *p_xt, *p_xbt, *p_h, *p_Wxp, *p_Wdt, *p_Wout, *p_Wbc;
    cudaGetSymbolAddress((void**)&p_z,   g_z);
    cudaGetSymbolAddress((void**)&p_xt,  g_xt);
    cudaGetSymbolAddress((void**)&p_xbt, g_xbt);
    cudaGetSymbolAddress((void**)&p_h,   g_h);
    cudaGetSymbolAddress((void**)&p_Bm,  g_Bm);
    cudaGetSymbolAddress((void**)&p_Cm,  g_Cm);
    cudaGetSymbolAddress((void**)&p_ax,  g_ax);
    cudaGetSymbolAddress((void**)&p_Y,   g_Yb);
    cudaGetSymbolAddress((void**)&p_cs,  g_cs);
    cudaGetSymbolAddress((void**)&p_dt,  g_dtot);
    cudaGetSymbolAddress((void**)&p_Ac,  g_Ac);
    cudaGetSymbolAddress((void**)&p_Wxp,  g_Wt_xp);
    cudaGetSymbolAddress((void**)&p_Wdt,  g_Wt_dt);
    cudaGetSymbolAddress((void**)&p_Wout, g_Wt_out);
    cudaGetSymbolAddress((void**)&p_Wbc,  g_Wt_bc);

    cudaFuncSetAttribute(mma_gemm_k<0>, cudaFuncAttributeMaxDynamicSharedMemorySize, GEMM_SMEM);
    cudaFuncSetAttribute(mma_gemm_k<3>, cudaFuncAttributeMaxDynamicSharedMemorySize, GEMM_SMEM);
    cudaFuncSetAttribute(dtbc_gemm_k,   cudaFuncAttributeMaxDynamicSharedMemorySize, GEMM_SMEM);

    // 0: A coefficient
    acoef_k<<<1, 512>>>(A_log, p_Ac);
    // 1: weight transposes + x -> fp16
    prep_k<<<5184, 256>>>(x, W_xproj, W_dt, W_out, W_B, W_C,
                          p_xt, p_Wxp, p_Wdt, p_Wout, p_Wbc);
    // 2: xproj: z -> p_z (fp32), fp16 x_bar -> p_xbt
    mma_gemm_k<3><<<dim3(8, 128), 256, GEMM_SMEM>>>(
        p_xt, p_Wxp, b_xproj, p_z, p_xbt, 512);
    // 3: merged dt-GEMM + fused B|C projection + rmsnorm (one wave)
    dtbc_gemm_k<<<dim3(5, 128), 256, GEMM_SMEM>>>(
        p_xbt, p_Wdt, p_Wbc, dt_bias, p_Ac, p_ax, p_Bm, p_Cm, g_Bn, g_Cn);
    // 4: intra-chunk recurrence (+ D_skip*x_bar folded)
    scan_intra_k<<<NBLK, 512>>>(p_xbt, p_Bm, p_Cm, D_skip, p_ax, p_Y, p_cs, p_dt);
    // 5: inter-chunk state scan
    state_scan_k<<<(BQ * NQ * 128) / 256, 256>>>(p_cs, p_dt);
    // 6: y += decay * (C @ prev_state)
    yinter_k<<<NBLK, 512>>>(p_Cm, p_cs, p_ax, p_Y);
    // 7: h = rmsnorm(y) * silu(z) -> fp16
    outnorm_k<<<MQ, 256>>>(p_Y, p_z, g_on, p_h);
    // 8: out = h @ W_out + b_out
    mma_gemm_k<0><<<dim3(4, 128), 256, GEMM_SMEM>>>(
        p_h, p_Wout, b_out, out, nullptr, 512);
}

// round 13
// speedup vs baseline: 1.4822x; 1.0282x over previous
#include <cuda_runtime.h>
#include <cuda_fp16.h>
#include <math.h>
#include <stdint.h>

// Problem constants (fixed shapes)
#define BQ 4
#define LQ 4096
#define DQ 512
#define NQ 64
#define MQ (BQ * LQ)        // 16384 rows
#define NBLK 256            // (b,chunk) blocks, chunk=64

typedef unsigned long long ull;

// -------- scratch (device globals; no allocation allowed) --------
__device__ __half g_zh[(size_t)MQ * 512];         // fp16 z half of xproj (ld 512)
__device__ __half g_xt[(size_t)MQ * 512];         // fp16 x
__device__ __half g_xbt[(size_t)MQ * 512];        // fp16 x_bar
__device__ __half g_h[(size_t)MQ * 512];          // fp16 h (outnorm output)
__device__ float  g_Bm[(size_t)MQ * 64];          // B proj (rmsnormed)
__device__ float  g_Cm[(size_t)MQ * 64];          // C proj (rmsnormed)
__device__ float  g_ax[(size_t)MQ * 512];         // a=exp(la) -> cumulative decay
__device__ float  g_Yb[(size_t)MQ * 512];         // y buffer (fp32)
__device__ float  g_cs[(size_t)NBLK * 64 * 512];  // chunk states -> prev states
__device__ float  g_dtot[(size_t)NBLK * 512];     // per-chunk total decay
__device__ float  g_Ac[512];                      // A coefficient
// transposed fp16 weights: Wt[n][k], k contiguous (512)
__device__ __half g_Wt_xp[1024 * 512];
__device__ __half g_Wt_dt[512 * 512];
__device__ __half g_Wt_out[512 * 512];
__device__ __half g_Wt_bc[128 * 512];             // rows 0..63 = W_B^T, 64..127 = W_C^T

// ============================ helpers ============================
__device__ __forceinline__ void mma_f16(float* d, const uint32_t* a,
                                        uint32_t b0, uint32_t b1) {
    asm volatile(
        "mma.sync.aligned.m16n8k16.row.col.f32.f16.f16.f32 "
        "{%0,%1,%2,%3}, {%4,%5,%6,%7}, {%8,%9}, {%0,%1,%2,%3};"
        : "+f"(d[0]), "+f"(d[1]), "+f"(d[2]), "+f"(d[3])
        : "r"(a[0]), "r"(a[1]), "r"(a[2]), "r"(a[3]), "r"(b0), "r"(b1));
}
__device__ __forceinline__ void ldsm4(uint32_t* r, uint32_t addr) {
    asm volatile("ldmatrix.sync.aligned.m8n8.x4.shared.b16 {%0,%1,%2,%3}, [%4];"
                 : "=r"(r[0]), "=r"(r[1]), "=r"(r[2]), "=r"(r[3]) : "r"(addr));
}
__device__ __forceinline__ float dt_transform(float v, float Acoef) {
    float sp  = (v > 20.0f) ? v : log1pf(expf(v));
    float dtv = fminf(fmaxf(sp, 1e-4f), 5.0f);
    float la  = fminf(fmaxf(dtv * Acoef, -18.4206807f), 0.0f);
    return expf(la);
}
__device__ __forceinline__ void cpasync16(uint32_t saddr, const void* g) {
    asm volatile("cp.async.cg.shared.global [%0], [%1], 16;" :: "r"(saddr), "l"(g));
}
#define CP_COMMIT() asm volatile("cp.async.commit_group;" ::: "memory")
#define CP_WAIT1()  asm volatile("cp.async.wait_group 1;" ::: "memory")
#define CP_WAIT0()  asm volatile("cp.async.wait_group 0;" ::: "memory")

__device__ __forceinline__ ull pack2(float lo, float hi) {
    ull r; asm("mov.b64 %0, {%1, %2};" : "=l"(r) : "f"(lo), "f"(hi)); return r;
}
__device__ __forceinline__ void unpack2(ull v, float& lo, float& hi) {
    asm("mov.b64 {%0, %1}, %2;" : "=f"(lo), "=f"(hi) : "l"(v));
}
#define FMA2_ACC(d, a, b) \
    asm("fma.rn.f32x2 %0, %1, %2, %0;" : "+l"(d) : "l"(a), "l"(b))
#define MUL2(d, a, b) \
    asm("mul.rn.f32x2 %0, %1, %2;" : "=l"(d) : "l"(a), "l"(b))

// ============================ fp16 GEMM mainloop (ldmatrix) ============================
// D[128,128] tile = A[row0..+128, 0..512) * Bt[col0..+128, 0..512)^T, fp16 in,
// fp32 accum.  BK=64 (8 chunks), 3 SMEM stages, 1 barrier/chunk.
// 8 warps (2 M x 4 N), warp tile 64x32, m16n8k16; fragments via ldmatrix.x4.
#define STG_F (128 * 36)    // words per stage
#define STG_B (STG_F * 4)   // bytes per stage
#define NSTG 3

__device__ __forceinline__ void gemm_mainloop(
    const __half* __restrict__ A, const __half* __restrict__ Bt,
    int row0, int col0, float* sm, float acc[4][4][4],
    int tid, int warp_m, int warp_n, int lane)
{
    float* Asm = sm;                 // NSTG stages x 128x36 words
    float* Bsm = sm + NSTG * STG_F;
    const uint32_t asm_u = (uint32_t)__cvta_generic_to_shared(Asm);
    const uint32_t bsm_u = (uint32_t)__cvta_generic_to_shared(Bsm);
    const int ldm = tid >> 3;
    const int ldc16 = tid & 7;       // 16B column within 128B row

    // strength-reduced load pointers / smem offsets
    const __half* pA[4];
    const __half* pB[4];
    uint32_t soff[4];
    #pragma unroll
    for (int j = 0; j < 4; j++) {
        const int m = ldm + 32 * j;
        pA[j] = A + (size_t)(row0 + m) * 512 + ldc16 * 8;
        pB[j] = Bt + (size_t)(col0 + m) * 512 + ldc16 * 8;
        soff[j] = (uint32_t)((m * 36 + ldc16 * 4) * 4);
    }

    auto issue = [&](int sByte, int k0) {
        #pragma unroll
        for (int j = 0; j < 4; j++) {
            cpasync16(asm_u + sByte + soff[j], pA[j] + k0);
            cpasync16(bsm_u + sByte + soff[j], pB[j] + k0);
        }
        CP_COMMIT();
    };
    issue(0, 0);
    issue(STG_B, 64);

    // ldmatrix lane geometry (byte offsets within a stage)
    const int a_row = warp_m * 64 + ((lane >> 3) & 1) * 8 + (lane & 7);
    const int a_col = (lane >> 4) * 4;                     // words
    uint32_t a_base[4];
    #pragma unroll
    for (int mi = 0; mi < 4; mi++)
        a_base[mi] = asm_u + (uint32_t)(((a_row + mi * 16) * 36 + a_col) * 4);
    const int b_row = warp_n * 32 + (lane >> 4) * 8 + (lane & 7);
    const int b_col = ((lane >> 3) & 1) * 4;               // words
    uint32_t b_base[2];
    #pragma unroll
    for (int nj = 0; nj < 2; nj++)
        b_base[nj] = bsm_u + (uint32_t)(((b_row + nj * 16) * 36 + b_col) * 4);

    uint32_t sByte = 0;              // compute stage byte offset
    uint32_t sIByte = 2 * STG_B;     // issue stage byte offset (stage 2 first)

    #pragma unroll 1
    for (int c = 0; c < 8; c++) {
        if (c < 7) { CP_WAIT1(); } else { CP_WAIT0(); }
        __syncthreads();
        if (c < 6) {
            issue(sIByte, (c + 2) * 64);
            sIByte = (sIByte == 2 * STG_B) ? 0u : sIByte + STG_B;
        }
        #pragma unroll
        for (int kk = 0; kk < 4; kk++) {
            const uint32_t koff = sByte + kk * 32;   // 8 words = 32B per k-step
            uint32_t af[4][4];
            #pragma unroll
            for (int mi = 0; mi < 4; mi++)
                ldsm4(af[mi], a_base[mi] + koff);
            uint32_t bf[2][4];
            #pragma unroll
            for (int nj = 0; nj < 2; nj++)
                ldsm4(bf[nj], b_base[nj] + koff);
            #pragma unroll
            for (int ni = 0; ni < 4; ni++) {
                const uint32_t b0 = bf[ni >> 1][(ni & 1) * 2];
                const uint32_t b1 = bf[ni >> 1][(ni & 1) * 2 + 1];
                #pragma unroll
                for (int mi = 0; mi < 4; mi++)
                    mma_f16(acc[mi][ni], af[mi], b0, b1);
            }
        }
        sByte = (sByte == 2 * STG_B) ? 0u : sByte + STG_B;
    }
    __syncthreads();
}

// ---- EPI 0: +bias -> fout (ldc, fp32).
// ---- EPI 3: xproj: +bias; n<512 -> fp16 x_bar to hout (ld 512);
//             n>=512 -> fp16 z to zout (ld 512, col n-512).
template <int EPI>
__global__ void __launch_bounds__(256, 2)
mma_gemm_k(const __half* __restrict__ A,
           const __half* __restrict__ Bt,
           const float* __restrict__ bias,
           float* __restrict__ fout, __half* __restrict__ hout,
           __half* __restrict__ zout, int ldc)
{
    extern __shared__ float sm[];
    const int tid = threadIdx.x;
    const int wid = tid >> 5;
    const int lane = tid & 31;
    const int g = lane >> 2;
    const int tig = lane & 3;
    const int warp_m = wid >> 2;
    const int warp_n = wid & 3;
    const int row0 = blockIdx.y * 128;
    const int col0 = blockIdx.x * 128;

    float acc[4][4][4] = {};
    gemm_mainloop(A, Bt, row0, col0, sm, acc, tid, warp_m, warp_n, lane);

    #pragma unroll
    for (int mi = 0; mi < 4; mi++) {
        const int m = row0 + warp_m * 64 + mi * 16 + g;
        #pragma unroll
        for (int ni = 0; ni < 4; ni++) {
            const int n = col0 + warp_n * 32 + ni * 8 + 2 * tig;
            float d0 = acc[mi][ni][0], d1 = acc[mi][ni][1];
            float d2 = acc[mi][ni][2], d3 = acc[mi][ni][3];
            const float b0 = bias[n], b1 = bias[n + 1];
            d0 += b0; d1 += b1; d2 += b0; d3 += b1;
            if (EPI == 3) {
                if (n < 512) {
                    *(__half2*)&hout[(size_t)m * 512 + n] = __floats2half2_rn(d0, d1);
                    *(__half2*)&hout[(size_t)(m + 8) * 512 + n] = __floats2half2_rn(d2, d3);
                } else {
                    *(__half2*)&zout[(size_t)m * 512 + n - 512] = __floats2half2_rn(d0, d1);
                    *(__half2*)&zout[(size_t)(m + 8) * 512 + n - 512] = __floats2half2_rn(d2, d3);
                }
            } else {
                *(float2*)&fout[(size_t)m * ldc + n] = make_float2(d0, d1);
                *(float2*)&fout[(size_t)(m + 8) * ldc + n] = make_float2(d2, d3);
            }
        }
    }
}

// ---- merged dt (blockIdx.x<4) + fused B|C rmsnorm (blockIdx.x==4) ----
__global__ void __launch_bounds__(256, 2)
dtbc_gemm_k(const __half* __restrict__ xbt,
            const __half* __restrict__ Wdt, const __half* __restrict__ Wbc,
            const float* __restrict__ dt_bias, const float* __restrict__ Ac,
            float* __restrict__ ax,
            float* __restrict__ Bm, float* __restrict__ Cm,
            const float* __restrict__ gBn, const float* __restrict__ gCn)
{
    extern __shared__ float sm[];
    __shared__ float ssred[256];
    const int tid = threadIdx.x;
    const int wid = tid >> 5;
    const int lane = tid & 31;
    const int g = lane >> 2;
    const int tig = lane & 3;
    const int warp_m = wid >> 2;
    const int warp_n = wid & 3;
    const int row0 = blockIdx.y * 128;
    const bool is_dt = blockIdx.x < 4;
    const int col0 = is_dt ? blockIdx.x * 128 : 0;
    const __half* Bt = is_dt ? Wdt : Wbc;

    if (!is_dt) ssred[tid] = 0.0f;

    float acc[4][4][4] = {};
    gemm_mainloop(xbt, Bt, row0, col0, sm, acc, tid, warp_m, warp_n, lane);

    if (is_dt) {
        #pragma unroll
        for (int mi = 0; mi < 4; mi++) {
            const int m = row0 + warp_m * 64 + mi * 16 + g;
            #pragma unroll
            for (int ni = 0; ni < 4; ni++) {
                const int n = col0 + warp_n * 32 + ni * 8 + 2 * tig;
                const float b0 = dt_bias[n], b1 = dt_bias[n + 1];
                const float a0 = Ac[n], a1 = Ac[n + 1];
                *(float2*)&ax[(size_t)m * 512 + n] = make_float2(
                    dt_transform(acc[mi][ni][0] + b0, a0),
                    dt_transform(acc[mi][ni][1] + b1, a1));
                *(float2*)&ax[(size_t)(m + 8) * 512 + n] = make_float2(
                    dt_transform(acc[mi][ni][2] + b0, a0),
                    dt_transform(acc[mi][ni][3] + b1, a1));
            }
        }
    } else {
        const int half = warp_n >> 1;                 // 0 = B, 1 = C
        #pragma unroll
        for (int mi = 0; mi < 4; mi++) {
            float s0 = 0.0f, s1 = 0.0f;
            #pragma unroll
            for (int ni = 0; ni < 4; ni++) {
                s0 += acc[mi][ni][0] * acc[mi][ni][0] + acc[mi][ni][1] * acc[mi][ni][1];
                s1 += acc[mi][ni][2] * acc[mi][ni][2] + acc[mi][ni][3] * acc[mi][ni][3];
            }
            s0 += __shfl_xor_sync(0xffffffffu, s0, 1);
            s0 += __shfl_xor_sync(0xffffffffu, s0, 2);
            s1 += __shfl_xor_sync(0xffffffffu, s1, 1);
            s1 += __shfl_xor_sync(0xffffffffu, s1, 2);
            if (tig == 0) {
                const int r = warp_m * 64 + mi * 16 + g;
                atomicAdd(&ssred[half * 128 + r], s0);
                atomicAdd(&ssred[half * 128 + r + 8], s1);
            }
        }
        __syncthreads();
        const float* gam = half ? gCn : gBn;
        float* outp = half ? Cm : Bm;
        #pragma unroll
        for (int mi = 0; mi < 4; mi++) {
            const int r = warp_m * 64 + mi * 16 + g;
            const float rs0 = rsqrtf(ssred[half * 128 + r] * (1.0f / 64.0f) + 1e-6f);
            const float rs1 = rsqrtf(ssred[half * 128 + r + 8] * (1.0f / 64.0f) + 1e-6f);
            #pragma unroll
            for (int ni = 0; ni < 4; ni++) {
                const int nl = (warp_n - half * 2) * 32 + ni * 8 + 2 * tig;  // 0..63
                const float g0 = gam[nl], g1 = gam[nl + 1];
                *(float2*)&outp[(size_t)(row0 + r) * 64 + nl] =
                    make_float2(acc[mi][ni][0] * rs0 * g0, acc[mi][ni][1] * rs0 * g1);
                *(float2*)&outp[(size_t)(row0 + r + 8) * 64 + nl] =
                    make_float2(acc[mi][ni][2] * rs1 * g0, acc[mi][ni][3] * rs1 * g1);
            }
        }
    }
}

// ============================ prep kernel ============================
// [0,4096): x -> fp16 xt (8 floats/thread). [4096,5184): weight transposes.
// [5184]: A coefficient.
__global__ void __launch_bounds__(256)
prep_k(const float* __restrict__ x,
       const float* __restrict__ Wxp, const float* __restrict__ Wdt,
       const float* __restrict__ Wout, const float* __restrict__ WB,
       const float* __restrict__ WC, const float* __restrict__ A_log,
       __half* __restrict__ xt, __half* __restrict__ Twxp, __half* __restrict__ Twdt,
       __half* __restrict__ Twout, __half* __restrict__ Twbc, float* __restrict__ Ac)
{
    int bid = blockIdx.x;
    if (bid < 4096) {
        const size_t gi = (size_t)bid * 256 + threadIdx.x;   // 8-float group
        float4 v0 = ((const float4*)x)[gi * 2];
        float4 v1 = ((const float4*)x)[gi * 2 + 1];
        __half2 h0 = __floats2half2_rn(v0.x, v0.y);
        __half2 h1 = __floats2half2_rn(v0.z, v0.w);
        __half2 h2 = __floats2half2_rn(v1.x, v1.y);
        __half2 h3 = __floats2half2_rn(v1.z, v1.w);
        uint4 u;
        u.x = *(uint32_t*)&h0; u.y = *(uint32_t*)&h1;
        u.z = *(uint32_t*)&h2; u.w = *(uint32_t*)&h3;
        ((uint4*)xt)[gi] = u;
        return;
    }
    if (bid == 5184) {
        const int d0 = threadIdx.x;
        Ac[d0]       = -expf(fminf(fmaxf(A_log[d0], -20.0f), 2.0f));
        Ac[d0 + 256] = -expf(fminf(fmaxf(A_log[d0 + 256], -20.0f), 2.0f));
        return;
    }
    bid -= 4096;
    const float* W; __half* Wt; int N, lb;
    if (bid < 512)       { W = Wxp;  Wt = Twxp;            N = 1024; lb = bid; }
    else if (bid < 768)  { W = Wdt;  Wt = Twdt;            N = 512;  lb = bid - 512; }
    else if (bid < 1024) { W = Wout; Wt = Twout;           N = 512;  lb = bid - 768; }
    else if (bid < 1056) { W = WB;   Wt = Twbc;            N = 64;   lb = bid - 1024; }
    else                 { W = WC;   Wt = Twbc + 64 * 512; N = 64;   lb = bid - 1056; }
    const int tiles_n = N / 32;
    const int n0 = (lb % tiles_n) * 32;
    const int k0 = (lb / tiles_n) * 32;
    __shared__ float tile[32][33];
    const int tx = threadIdx.x & 31, ty = threadIdx.x >> 5;
    for (int i = ty; i < 32; i += 8)
        tile[i][tx] = W[(size_t)(k0 + i) * N + n0 + tx];
    __syncthreads();
    for (int i = ty; i < 32; i += 8)
        Wt[(size_t)(n0 + i) * 512 + k0 + tx] = __float2half_rn(tile[tx][i]);
}

// ============================ scan kernels ============================

// Intra-chunk recurrence (f32x2, LDS.128 tile reads, prefetch).
// Y gets y_intra + D_skip*x_bar; x_bar from fp16 xbt (ld 512).
__global__ void __launch_bounds__(512)
scan_intra_k(const __half* __restrict__ xbt, const float* __restrict__ Bm,
             const float* __restrict__ Cm, const float* __restrict__ Dskip,
             float* __restrict__ ax, float* __restrict__ Y,
             float* __restrict__ cs, float* __restrict__ dtot)
{
    __shared__ float4 Bs[64][16];
    __shared__ float4 Cs[64][16];
    const int blk = blockIdx.x;
    const int d = threadIdx.x;
    const size_t l0 = (size_t)blk * 64;

    for (int t = d; t < 64 * 16; t += 512) {
        int r = t >> 4, c = t & 15;
        Bs[r][c] = ((const float4*)Bm)[(l0 + r) * 16 + c];
        Cs[r][c] = ((const float4*)Cm)[(l0 + r) * 16 + c];
    }
    __syncthreads();

    ull S2[32];
    #pragma unroll
    for (int q = 0; q < 32; q++) S2[q] = 0ull;
    float dec = 1.0f;
    const float dsk = Dskip[d];

    const float* axp = ax + l0 * 512 + d;
    const __half* xpp = xbt + l0 * 512 + d;
    float av = axp[0];
    float xv = __half2float(xpp[0]);

    #pragma unroll 1
    for (int i = 0; i < 64; i++) {
        float av_n = 0.0f, xv_n = 0.0f;
        if (i < 63) {
            av_n = axp[(size_t)(i + 1) * 512];
            xv_n = __half2float(xpp[(size_t)(i + 1) * 512]);
        }
        const size_t m = l0 + i;
        dec *= av;
        ax[m * 512 + d] = dec;
        const ull av2 = pack2(av, av);
        const ull xv2 = pack2(xv, xv);
        const ulonglong2* Bp2 = (const ulonglong2*)&Bs[i][0];
        const ulonglong2* Cp2 = (const ulonglong2*)&Cs[i][0];
        ull y2 = 0ull;
        #pragma unroll
        for (int q2 = 0; q2 < 16; q2++) {
            const ulonglong2 b2 = Bp2[q2];
            const ulonglong2 c2 = Cp2[q2];
            ull bx0; MUL2(bx0, b2.x, xv2);
            FMA2_ACC(bx0, av2, S2[2 * q2]);
            S2[2 * q2] = bx0;
            FMA2_ACC(y2, c2.x, S2[2 * q2]);
            ull bx1; MUL2(bx1, b2.y, xv2);
            FMA2_ACC(bx1, av2, S2[2 * q2 + 1]);
            S2[2 * q2 + 1] = bx1;
            FMA2_ACC(y2, c2.y, S2[2 * q2 + 1]);
        }
        float ylo, yhi; unpack2(y2, ylo, yhi);
        Y[m * 512 + d] = ylo + yhi + dsk * xv;
        av = av_n; xv = xv_n;
    }

    #pragma unroll
    for (int q = 0; q < 32; q++) {
        float slo, shi; unpack2(S2[q], slo, shi);
        cs[((size_t)blk * 64 + 2 * q) * 512 + d] = slo;
        cs[((size_t)blk * 64 + 2 * q + 1) * 512 + d] = shi;
    }
    dtot[(size_t)blk * 512 + d] = dec;
}

// Inter-chunk state scan (prefetch), float4 over d; cs -> prev_state in place.
__global__ void state_scan_k(float* __restrict__ cs, const float* __restrict__ dtot)
{
    const int idx = blockIdx.x * blockDim.x + threadIdx.x;   // B*N*128 = 32768
    const int d4 = idx & 127;
    const int n = (idx >> 7) & 63;
    const int b = idx >> 13;
    float4* cs4 = (float4*)cs;
    const float4* dt4 = (const float4*)dtot;
    float4 s = make_float4(0.f, 0.f, 0.f, 0.f);

    size_t off = ((size_t)(b * 64) * 64 + n) * 128 + d4;
    float4 v = cs4[off];
    float4 a = dt4[(size_t)(b * 64) * 128 + d4];

    #pragma unroll 1
    for (int ch = 0; ch < 64; ch++) {
        float4 vn, an;
        if (ch < 63) {
            const int blkn = b * 64 + ch + 1;
            vn = cs4[((size_t)blkn * 64 + n) * 128 + d4];
            an = dt4[(size_t)blkn * 128 + d4];
        } else { vn = s; an = s; }
        cs4[off] = s;
        s.x = fmaf(s.x, a.x, v.x);
        s.y = fmaf(s.y, a.y, v.y);
        s.z = fmaf(s.z, a.z, v.z);
        s.w = fmaf(s.w, a.w, v.w);
        off = ((size_t)(b * 64 + ch + 1) * 64 + n) * 128 + d4;
        v = vn; a = an;
    }
}

// y += decay * (C @ prev_state)   (f32x2, LDS.128 tile reads)
__global__ void __launch_bounds__(512)
yinter_k(const float* __restrict__ Cm, const float* __restrict__ ps,
         const float* __restrict__ decay, float* __restrict__ Y)
{
    __shared__ float4 Cs[64][16];
    const int blk = blockIdx.x;
    const int d = threadIdx.x;
    const size_t l0 = (size_t)blk * 64;

    for (int t = d; t < 64 * 16; t += 512) {
        int r = t >> 4, c = t & 15;
        Cs[r][c] = ((const float4*)Cm)[(l0 + r) * 16 + c];
    }
    __syncthreads();

    ull PS2[32];
    #pragma unroll
    for (int q = 0; q < 32; q++)
        PS2[q] = pack2(ps[((size_t)blk * 64 + 2 * q) * 512 + d],
                       ps[((size_t)blk * 64 + 2 * q + 1) * 512 + d]);

    float dc = decay[l0 * 512 + d];
    float yv = Y[l0 * 512 + d];

    #pragma unroll 1
    for (int i = 0; i < 64; i++) {
        float dc_n = 0.0f, yv_n = 0.0f;
        if (i < 63) {
            dc_n = decay[(l0 + i + 1) * 512 + d];
            yv_n = Y[(l0 + i + 1) * 512 + d];
        }
        const ulonglong2* Cp2 = (const ulonglong2*)&Cs[i][0];
        ull y2 = 0ull;
        #pragma unroll
        for (int q2 = 0; q2 < 16; q2++) {
            const ulonglong2 c2 = Cp2[q2];
            FMA2_ACC(y2, c2.x, PS2[2 * q2]);
            FMA2_ACC(y2, c2.y, PS2[2 * q2 + 1]);
        }
        float ylo, yhi; unpack2(y2, ylo, yhi);
        Y[(l0 + i) * 512 + d] = yv + dc * (ylo + yhi);
        dc = dc_n; yv = yv_n;
    }
}

// h = fp16(rmsnorm(y, g) * silu(z)) -> hbuf; z fp16 (ld 512).
__global__ void outnorm_k(const float* __restrict__ Y, const __half* __restrict__ zb,
                          const float* __restrict__ g, __half* __restrict__ hb)
{
    __shared__ float wsum[8];
    const int m = blockIdx.x;
    const int t = threadIdx.x;
    const int lane = t & 31, w = t >> 5;
    float v0 = Y[(size_t)m * 512 + t];
    float v1 = Y[(size_t)m * 512 + t + 256];
    float ss = v0 * v0 + v1 * v1;
    #pragma unroll
    for (int o = 16; o; o >>= 1) ss += __shfl_xor_sync(0xffffffffu, ss, o);
    if (lane == 0) wsum[w] = ss;
    __syncthreads();
    float tot = wsum[0];
    #pragma unroll
    for (int j = 1; j < 8; j++) tot += wsum[j];
    float rs = rsqrtf(tot * (1.0f / 512.0f) + 1e-6f);
    float z0 = __half2float(zb[(size_t)m * 512 + t]);
    float z1 = __half2float(zb[(size_t)m * 512 + t + 256]);
    float s0 = z0 / (1.0f + expf(-z0));
    float s1 = z1 / (1.0f + expf(-z1));
    hb[(size_t)m * 512 + t]       = __float2half_rn(v0 * rs * g[t] * s0);
    hb[(size_t)m * 512 + t + 256] = __float2half_rn(v1 * rs * g[t + 256] * s1);
}

// ============================ launch ============================
#define GEMM_SMEM (NSTG * STG_F * 4 * 2)   // 110592 bytes

extern "C" void kernel_launch(void* const* d_in, const int* in_sizes, int n_in,
                              void* d_out, int out_size)
{
    const float* x       = (const float*)d_in[0];
    const float* A_log   = (const float*)d_in[1];
    const float* dt_bias = (const float*)d_in[2];
    const float* D_skip  = (const float*)d_in[3];
    const float* W_xproj = (const float*)d_in[4];
    const float* b_xproj = (const float*)d_in[5];
    const float* W_B     = (const float*)d_in[6];
    const float* W_C     = (const float*)d_in[7];
    const float* W_dt    = (const float*)d_in[8];
    const float* g_Bn    = (const float*)d_in[9];
    const float* g_Cn    = (const float*)d_in[10];
    const float* g_on    = (const float*)d_in[11];
    const float* W_out   = (const float*)d_in[12];
    const float* b_out   = (const float*)d_in[13];
    float* out = (float*)d_out;

    float *p_Bm, *p_Cm, *p_ax, *p_Y, *p_cs, *p_dt, *p_Ac;
    __half *p_zh, *p_xt, *p_xbt, *p_h, *p_Wxp, *p_Wdt, *p_Wout, *p_Wbc;
    cudaGetSymbolAddress((void**)&p_zh,  g_zh);
    cudaGetSymbolAddress((void**)&p_xt,  g_xt);
    cudaGetSymbolAddress((void**)&p_xbt, g_xbt);
    cudaGetSymbolAddress((void**)&p_h,   g_h);
    cudaGetSymbolAddress((void**)&p_Bm,  g_Bm);
    cudaGetSymbolAddress((void**)&p_Cm,  g_Cm);
    cudaGetSymbolAddress((void**)&p_ax,  g_ax);
    cudaGetSymbolAddress((void**)&p_Y,   g_Yb);
    cudaGetSymbolAddress((void**)&p_cs,  g_cs);
    cudaGetSymbolAddress((void**)&p_dt,  g_dtot);
    cudaGetSymbolAddress((void**)&p_Ac,  g_Ac);
    cudaGetSymbolAddress((void**)&p_Wxp,  g_Wt_xp);
    cudaGetSymbolAddress((void**)&p_Wdt,  g_Wt_dt);
    cudaGetSymbolAddress((void**)&p_Wout, g_Wt_out);
    cudaGetSymbolAddress((void**)&p_Wbc,  g_Wt_bc);

    cudaFuncSetAttribute(mma_gemm_k<0>, cudaFuncAttributeMaxDynamicSharedMemorySize, GEMM_SMEM);
    cudaFuncSetAttribute(mma_gemm_k<3>, cudaFuncAttributeMaxDynamicSharedMemorySize, GEMM_SMEM);
    cudaFuncSetAttribute(dtbc_gemm_k,   cudaFuncAttributeMaxDynamicSharedMemorySize, GEMM_SMEM);

    // 0: prep (x->fp16, weight transposes, A coefficient)
    prep_k<<<5185, 256>>>(x, W_xproj, W_dt, W_out, W_B, W_C, A_log,
                          p_xt, p_Wxp, p_Wdt, p_Wout, p_Wbc, p_Ac);
    // 1: xproj: fp16 z -> p_zh, fp16 x_bar -> p_xbt
    mma_gemm_k<3><<<dim3(8, 128), 256, GEMM_SMEM>>>(
        p_xt, p_Wxp, b_xproj, nullptr, p_xbt, p_zh, 512);
    // 2: merged dt-GEMM + fused B|C projection + rmsnorm (one wave)
    dtbc_gemm_k<<<dim3(5, 128), 256, GEMM_SMEM>>>(
        p_xbt, p_Wdt, p_Wbc, dt_bias, p_Ac, p_ax, p_Bm, p_Cm, g_Bn, g_Cn);
    // 3: intra-chunk recurrence (+ D_skip*x_bar folded)
    scan_intra_k<<<NBLK, 512>>>(p_xbt, p_Bm, p_Cm, D_skip, p_ax, p_Y, p_cs, p_dt);
    // 4: inter-chunk state scan
    state_scan_k<<<(BQ * NQ * 128) / 256, 256>>>(p_cs, p_dt);
    // 5: y += decay * (C @ prev_state)
    yinter_k<<<NBLK, 512>>>(p_Cm, p_cs, p_ax, p_Y);
    // 6: h = rmsnorm(y) * silu(z) -> fp16
    outnorm_k<<<MQ, 256>>>(p_Y, p_zh, g_on, p_h);
    // 7: out = h @ W_out + b_out
    mma_gemm_k<0><<<dim3(4, 128), 256, GEMM_SMEM>>>(
        p_h, p_Wout, b_out, out, nullptr, nullptr, 512);
}